// round 5
// baseline (speedup 1.0000x reference)
#include <cuda_runtime.h>
#include <cuda_fp16.h>
#include <cstdint>

#define NMAX 1048576
#define EMAX 4194304
#define DD   32
#define RR   4

// Scratch (__device__ globals; no allocation allowed in kernel_launch)
__device__ __half g_hw[(size_t)NMAX * RR * DD];  // 256 MB fp16 messages hw[n*4+r][o]
__device__ float  g_aggA[(size_t)NMAX * DD];     // 128 MB
__device__ float  g_aggB[(size_t)NMAX * DD];     // 128 MB
// CSR-by-dst build
__device__ int g_counts[NMAX];        // histogram, then scatter cursor
__device__ int g_starts[NMAX + 1];
__device__ int g_blocksums[1024];
__device__ int g_eidx[EMAX];          // packed (src<<2)|etype, grouped by dst

// ---------------------------------------------------------------------------
__device__ __forceinline__ unsigned pack_h2(float a, float b) {
    __half2 h = __floats2half2_rn(a, b);
    return *reinterpret_cast<unsigned*>(&h);
}

__device__ __forceinline__ void mma16816(float c[4], const unsigned a[4], const unsigned b[2]) {
    asm volatile("mma.sync.aligned.m16n8k16.row.col.f32.f16.f16.f32 "
                 "{%0,%1,%2,%3}, {%4,%5,%6,%7}, {%8,%9}, {%0,%1,%2,%3};"
                 : "+f"(c[0]), "+f"(c[1]), "+f"(c[2]), "+f"(c[3])
                 : "r"(a[0]), "r"(a[1]), "r"(a[2]), "r"(a[3]),
                   "r"(b[0]), "r"(b[1]));
}

__device__ __forceinline__ float wcat(const float* __restrict__ W,
                                      const float* __restrict__ Wl,
                                      int k, int c) {
    return (c < 128) ? __ldg(W + (c >> 5) * 1024 + k * 32 + (c & 31))
                     : __ldg(Wl + k * 32 + (c - 128));
}

// ---------------------------------------------------------------------------
// proj via tensor cores (warp computes [16 nodes x 160 cols], 40 HMMA)
// ---------------------------------------------------------------------------
template <bool RELU_IN>
__global__ void __launch_bounds__(256)
proj_mma(const float* __restrict__ hin,
         const float* __restrict__ W, const float* __restrict__ Wl,
         const float* __restrict__ bias,
         __half* __restrict__ hw, float* __restrict__ agg, int nTiles)
{
    const int lane   = threadIdx.x & 31;
    const int warpId = (blockIdx.x * blockDim.x + threadIdx.x) >> 5;
    const int nWarps = (gridDim.x * blockDim.x) >> 5;
    const int kq = 2 * (lane & 3);
    const int nq = lane >> 2;

    unsigned bf[20][2][2];
#pragma unroll
    for (int g = 0; g < 20; g++)
#pragma unroll
        for (int s = 0; s < 2; s++) {
            const int c  = 8 * g + nq;
            const int k0 = 16 * s + kq;
            bf[g][s][0] = pack_h2(wcat(W, Wl, k0,     c), wcat(W, Wl, k0 + 1, c));
            bf[g][s][1] = pack_h2(wcat(W, Wl, k0 + 8, c), wcat(W, Wl, k0 + 9, c));
        }

    float2 bvec[4];
#pragma unroll
    for (int gg = 0; gg < 4; gg++) {
        const int o = 8 * gg + kq;
        bvec[gg] = make_float2(__ldg(bias + o), __ldg(bias + o + 1));
    }

    for (int t = warpId; t < nTiles; t += nWarps) {
        const int m0 = t * 16;
        const float* r0 = hin + (size_t)(m0 + nq) * DD + kq;
        const float* r1 = r0 + 8 * DD;

        float2 x0a = *(const float2*)(r0);
        float2 x0b = *(const float2*)(r0 + 8);
        float2 x0c = *(const float2*)(r0 + 16);
        float2 x0d = *(const float2*)(r0 + 24);
        float2 x1a = *(const float2*)(r1);
        float2 x1b = *(const float2*)(r1 + 8);
        float2 x1c = *(const float2*)(r1 + 16);
        float2 x1d = *(const float2*)(r1 + 24);

        if (RELU_IN) {
            x0a.x = fmaxf(x0a.x, 0.f); x0a.y = fmaxf(x0a.y, 0.f);
            x0b.x = fmaxf(x0b.x, 0.f); x0b.y = fmaxf(x0b.y, 0.f);
            x0c.x = fmaxf(x0c.x, 0.f); x0c.y = fmaxf(x0c.y, 0.f);
            x0d.x = fmaxf(x0d.x, 0.f); x0d.y = fmaxf(x0d.y, 0.f);
            x1a.x = fmaxf(x1a.x, 0.f); x1a.y = fmaxf(x1a.y, 0.f);
            x1b.x = fmaxf(x1b.x, 0.f); x1b.y = fmaxf(x1b.y, 0.f);
            x1c.x = fmaxf(x1c.x, 0.f); x1c.y = fmaxf(x1c.y, 0.f);
            x1d.x = fmaxf(x1d.x, 0.f); x1d.y = fmaxf(x1d.y, 0.f);
        }

        unsigned A0[4] = { pack_h2(x0a.x, x0a.y), pack_h2(x1a.x, x1a.y),
                           pack_h2(x0b.x, x0b.y), pack_h2(x1b.x, x1b.y) };
        unsigned A1[4] = { pack_h2(x0c.x, x0c.y), pack_h2(x1c.x, x1c.y),
                           pack_h2(x0d.x, x0d.y), pack_h2(x1d.x, x1d.y) };

        float acc[20][4];
#pragma unroll
        for (int g = 0; g < 20; g++) {
            acc[g][0] = 0.f; acc[g][1] = 0.f; acc[g][2] = 0.f; acc[g][3] = 0.f;
        }
#pragma unroll
        for (int g = 0; g < 20; g++) {
            mma16816(acc[g], A0, bf[g][0]);
            mma16816(acc[g], A1, bf[g][1]);
        }

        __half* hw0 = hw + (size_t)(m0 + nq) * 128 + kq;
        __half* hw1 = hw + (size_t)(m0 + nq + 8) * 128 + kq;
#pragma unroll
        for (int g = 0; g < 16; g++) {
            *reinterpret_cast<__half2*>(hw0 + 8 * g) = __floats2half2_rn(acc[g][0], acc[g][1]);
            *reinterpret_cast<__half2*>(hw1 + 8 * g) = __floats2half2_rn(acc[g][2], acc[g][3]);
        }
        float* ag0 = agg + (size_t)(m0 + nq) * DD + kq;
        float* ag1 = agg + (size_t)(m0 + nq + 8) * DD + kq;
#pragma unroll
        for (int gg = 0; gg < 4; gg++) {
            const int g = 16 + gg;
            *reinterpret_cast<float2*>(ag0 + 8 * gg) =
                make_float2(acc[g][0] + bvec[gg].x, acc[g][1] + bvec[gg].y);
            *reinterpret_cast<float2*>(ag1 + 8 * gg) =
                make_float2(acc[g][2] + bvec[gg].x, acc[g][3] + bvec[gg].y);
        }
    }
}

// ---------------------------------------------------------------------------
// CSR-by-dst build: histogram -> 2-level exclusive scan -> scatter
// ---------------------------------------------------------------------------
__global__ void hist_kernel(const int* __restrict__ dst, int E) {
    int e = blockIdx.x * blockDim.x + threadIdx.x;
    if (e < E) atomicAdd(&g_counts[__ldg(dst + e)], 1);
}

__global__ void __launch_bounds__(1024)
scan1_kernel(int N) {
    __shared__ int wsum[32];
    const int i = blockIdx.x * 1024 + threadIdx.x;
    const int lane = threadIdx.x & 31, wid = threadIdx.x >> 5;
    int v = (i < N) ? g_counts[i] : 0;
    int x = v;
#pragma unroll
    for (int o = 1; o < 32; o <<= 1) {
        int y = __shfl_up_sync(0xffffffffu, x, o);
        if (lane >= o) x += y;
    }
    if (lane == 31) wsum[wid] = x;
    __syncthreads();
    if (threadIdx.x < 32) {
        int s = wsum[threadIdx.x];
        int t = s;
#pragma unroll
        for (int o = 1; o < 32; o <<= 1) {
            int y = __shfl_up_sync(0xffffffffu, t, o);
            if (threadIdx.x >= o) t += y;
        }
        wsum[threadIdx.x] = t - s;           // exclusive warp base
        if (threadIdx.x == 31) g_blocksums[blockIdx.x] = t;
    }
    __syncthreads();
    if (i < N) g_starts[i] = x - v + wsum[wid];
}

__global__ void __launch_bounds__(1024)
scan2_kernel(int nb) {
    __shared__ int wsum[32];
    const int i = threadIdx.x;
    const int lane = i & 31, wid = i >> 5;
    int v = (i < nb) ? g_blocksums[i] : 0;
    int x = v;
#pragma unroll
    for (int o = 1; o < 32; o <<= 1) {
        int y = __shfl_up_sync(0xffffffffu, x, o);
        if (lane >= o) x += y;
    }
    if (lane == 31) wsum[wid] = x;
    __syncthreads();
    if (i < 32) {
        int s = wsum[i];
        int t = s;
#pragma unroll
        for (int o = 1; o < 32; o <<= 1) {
            int y = __shfl_up_sync(0xffffffffu, t, o);
            if (i >= o) t += y;
        }
        wsum[i] = t - s;
    }
    __syncthreads();
    if (i < nb) g_blocksums[i] = x - v + wsum[wid];
}

__global__ void __launch_bounds__(1024)
scan3_kernel(int N, int E) {
    const int i = blockIdx.x * 1024 + threadIdx.x;
    if (i < N) {
        int s = g_starts[i] + g_blocksums[i >> 10];
        g_starts[i] = s;
        g_counts[i] = s;    // scatter cursor
    }
    if (i == 0) g_starts[N] = E;
}

__global__ void scatter_kernel(const int* __restrict__ src,
                               const int* __restrict__ dst,
                               const int* __restrict__ et, int E) {
    int e = blockIdx.x * blockDim.x + threadIdx.x;
    if (e >= E) return;
    int pos = atomicAdd(&g_counts[__ldg(dst + e)], 1);
    g_eidx[pos] = (__ldg(src + e) << 2) | __ldg(et + e);
}

// ---------------------------------------------------------------------------
// gather_agg: warp per node; agg[n] = base[n] + sum_{edges into n} hw[sidx]
// In-place on the base buffer (read-then-overwrite, no atomics).
// ---------------------------------------------------------------------------
__global__ void __launch_bounds__(256)
gather_agg_kernel(const __half* __restrict__ hw,
                  float* __restrict__ agg, int N)
{
    const int lane = threadIdx.x & 31;
    const int n = (blockIdx.x * blockDim.x + threadIdx.x) >> 5;
    if (n >= N) return;

    int j   = __ldg(g_starts + n);
    int end = __ldg(g_starts + n + 1);
    float acc = agg[(size_t)n * DD + lane];

    for (; j + 2 <= end; j += 2) {
        int s0 = __ldg(g_eidx + j);
        int s1 = __ldg(g_eidx + j + 1);
        float v0 = __half2float(__ldg(hw + (size_t)s0 * DD + lane));
        float v1 = __half2float(__ldg(hw + (size_t)s1 * DD + lane));
        acc += v0 + v1;
    }
    if (j < end) {
        int s0 = __ldg(g_eidx + j);
        acc += __half2float(__ldg(hw + (size_t)s0 * DD + lane));
    }
    agg[(size_t)n * DD + lane] = acc;
}

// ---------------------------------------------------------------------------
__global__ void mean_kernel(const float* __restrict__ agg,
                            float* __restrict__ out, int M)
{
    int lane = threadIdx.x & 31;
    int m = (blockIdx.x * blockDim.x + threadIdx.x) >> 5;
    if (m >= M) return;
    float s = 0.0f;
#pragma unroll
    for (int a = 0; a < 32; a++)
        s += fmaxf(agg[((size_t)m * 32 + a) * DD + lane], 0.0f);
    out[(size_t)m * DD + lane] = s * (1.0f / 32.0f);
}

// ---------------------------------------------------------------------------
extern "C" void kernel_launch(void* const* d_in, const int* in_sizes, int n_in,
                              void* d_out, int out_size)
{
    const float* x    = (const float*)d_in[0];
    const float* W    = (const float*)d_in[1];
    const float* Wl   = (const float*)d_in[2];
    const float* bias = (const float*)d_in[3];
    const int*   src  = (const int*)d_in[4];
    const int*   dst  = (const int*)d_in[5];
    const int*   et   = (const int*)d_in[6];
    float* out = (float*)d_out;

    const int N = in_sizes[0] / DD;
    const int E = in_sizes[4];
    const int M = out_size / DD;
    const int nTiles = N / 16;

    void *hwP = nullptr, *aP = nullptr, *bP = nullptr, *cP = nullptr;
    cudaGetSymbolAddress(&hwP, g_hw);
    cudaGetSymbolAddress(&aP, g_aggA);
    cudaGetSymbolAddress(&bP, g_aggB);
    cudaGetSymbolAddress(&cP, g_counts);
    __half* hwp = (__half*)hwP;
    float* aggA = (float*)aP;
    float* aggB = (float*)bP;

    const int eB  = (E + 255) / 256;
    const int nB1k = (N + 1023) / 1024;
    const int projBlocks = 1024;
    const int aggBlocks  = (N * 32 + 255) / 256;
    const int meanBlocks = (M * 32 + 255) / 256;

    // ---- Build CSR by dst (once per launch; reused by both layers) ----
    cudaMemsetAsync(cP, 0, (size_t)N * sizeof(int), 0);
    hist_kernel<<<eB, 256>>>(dst, E);
    scan1_kernel<<<nB1k, 1024>>>(N);
    scan2_kernel<<<1, 1024>>>(nB1k);
    scan3_kernel<<<nB1k, 1024>>>(N, E);
    scatter_kernel<<<eB, 256>>>(src, dst, et, E);

    // ---- Layer 1 ----
    proj_mma<false><<<projBlocks, 256>>>(x, W, Wl, bias, hwp, aggA, nTiles);
    gather_agg_kernel<<<aggBlocks, 256>>>(hwp, aggA, N);

    // ---- Layer 2 ----
    proj_mma<true><<<projBlocks, 256>>>(aggA, W, Wl, bias, hwp, aggB, nTiles);
    gather_agg_kernel<<<aggBlocks, 256>>>(hwp, aggB, N);

    // ---- Per-molecule mean ----
    mean_kernel<<<meanBlocks, 256>>>(aggB, out, M);
}

// round 6
// speedup vs baseline: 1.6554x; 1.6554x over previous
#include <cuda_runtime.h>
#include <cuda_fp16.h>
#include <cstdint>

#define NMAX 1048576
#define EMAX 4194304
#define DD   32
#define RR   4

// Scratch (__device__ globals; no allocation allowed in kernel_launch)
__device__ __half g_hw[(size_t)NMAX * RR * DD];  // 256 MB fp16 messages hw[n*4+r][o]
__device__ __half g_aggA[(size_t)NMAX * DD];     // 64 MB (L2-resident atomic target)
__device__ __half g_aggB[(size_t)NMAX * DD];     // 64 MB

// ---------------------------------------------------------------------------
__device__ __forceinline__ unsigned pack_h2(float a, float b) {
    __half2 h = __floats2half2_rn(a, b);
    return *reinterpret_cast<unsigned*>(&h);
}

__device__ __forceinline__ void mma16816(float c[4], const unsigned a[4], const unsigned b[2]) {
    asm volatile("mma.sync.aligned.m16n8k16.row.col.f32.f16.f16.f32 "
                 "{%0,%1,%2,%3}, {%4,%5,%6,%7}, {%8,%9}, {%0,%1,%2,%3};"
                 : "+f"(c[0]), "+f"(c[1]), "+f"(c[2]), "+f"(c[3])
                 : "r"(a[0]), "r"(a[1]), "r"(a[2]), "r"(a[3]),
                   "r"(b[0]), "r"(b[1]));
}

__device__ __forceinline__ float wcat(const float* __restrict__ W,
                                      const float* __restrict__ Wl,
                                      int k, int c) {
    return (c < 128) ? __ldg(W + (c >> 5) * 1024 + k * 32 + (c & 31))
                     : __ldg(Wl + k * 32 + (c - 128));
}

// ---------------------------------------------------------------------------
// proj via tensor cores: warp computes [16 nodes x 160 cols] with 40 HMMA.
//   hw[n][c] (c<128)  fp16 messages
//   agg[n][o] (fp16)  self-loop + bias  (atomic target base)
// TIN = float (layer 1 input) or __half (layer 2 reads fp16 agg, relu fused).
// ---------------------------------------------------------------------------
template <bool RELU_IN, typename TIN>
__global__ void __launch_bounds__(256)
proj_mma(const TIN* __restrict__ hin,
         const float* __restrict__ W, const float* __restrict__ Wl,
         const float* __restrict__ bias,
         __half* __restrict__ hw, __half* __restrict__ agg, int nTiles)
{
    const int lane   = threadIdx.x & 31;
    const int warpId = (blockIdx.x * blockDim.x + threadIdx.x) >> 5;
    const int nWarps = (gridDim.x * blockDim.x) >> 5;
    const int kq = 2 * (lane & 3);
    const int nq = lane >> 5 ? 0 : (lane >> 2);   // lane>>2 (kept simple below)

    const int row = lane >> 2;      // 0..7

    unsigned bf[20][2][2];
#pragma unroll
    for (int g = 0; g < 20; g++)
#pragma unroll
        for (int s = 0; s < 2; s++) {
            const int c  = 8 * g + row;
            const int k0 = 16 * s + kq;
            bf[g][s][0] = pack_h2(wcat(W, Wl, k0,     c), wcat(W, Wl, k0 + 1, c));
            bf[g][s][1] = pack_h2(wcat(W, Wl, k0 + 8, c), wcat(W, Wl, k0 + 9, c));
        }

    float2 bvec[4];
#pragma unroll
    for (int gg = 0; gg < 4; gg++) {
        const int o = 8 * gg + kq;
        bvec[gg] = make_float2(__ldg(bias + o), __ldg(bias + o + 1));
    }

    const __half2 zero2 = __float2half2_rn(0.0f);

    for (int t = warpId; t < nTiles; t += nWarps) {
        const int m0 = t * 16;
        unsigned A0[4], A1[4];

        if (sizeof(TIN) == 4) {
            const float* r0 = (const float*)hin + (size_t)(m0 + row) * DD + kq;
            const float* r1 = r0 + 8 * DD;
            float2 x0a = *(const float2*)(r0);
            float2 x0b = *(const float2*)(r0 + 8);
            float2 x0c = *(const float2*)(r0 + 16);
            float2 x0d = *(const float2*)(r0 + 24);
            float2 x1a = *(const float2*)(r1);
            float2 x1b = *(const float2*)(r1 + 8);
            float2 x1c = *(const float2*)(r1 + 16);
            float2 x1d = *(const float2*)(r1 + 24);
            if (RELU_IN) {
                x0a.x = fmaxf(x0a.x, 0.f); x0a.y = fmaxf(x0a.y, 0.f);
                x0b.x = fmaxf(x0b.x, 0.f); x0b.y = fmaxf(x0b.y, 0.f);
                x0c.x = fmaxf(x0c.x, 0.f); x0c.y = fmaxf(x0c.y, 0.f);
                x0d.x = fmaxf(x0d.x, 0.f); x0d.y = fmaxf(x0d.y, 0.f);
                x1a.x = fmaxf(x1a.x, 0.f); x1a.y = fmaxf(x1a.y, 0.f);
                x1b.x = fmaxf(x1b.x, 0.f); x1b.y = fmaxf(x1b.y, 0.f);
                x1c.x = fmaxf(x1c.x, 0.f); x1c.y = fmaxf(x1c.y, 0.f);
                x1d.x = fmaxf(x1d.x, 0.f); x1d.y = fmaxf(x1d.y, 0.f);
            }
            A0[0] = pack_h2(x0a.x, x0a.y); A0[1] = pack_h2(x1a.x, x1a.y);
            A0[2] = pack_h2(x0b.x, x0b.y); A0[3] = pack_h2(x1b.x, x1b.y);
            A1[0] = pack_h2(x0c.x, x0c.y); A1[1] = pack_h2(x1c.x, x1c.y);
            A1[2] = pack_h2(x0d.x, x0d.y); A1[3] = pack_h2(x1d.x, x1d.y);
        } else {
            const __half* r0 = (const __half*)hin + (size_t)(m0 + row) * DD + kq;
            const __half* r1 = r0 + 8 * DD;
            __half2 h0a = *(const __half2*)(r0);
            __half2 h0b = *(const __half2*)(r0 + 8);
            __half2 h0c = *(const __half2*)(r0 + 16);
            __half2 h0d = *(const __half2*)(r0 + 24);
            __half2 h1a = *(const __half2*)(r1);
            __half2 h1b = *(const __half2*)(r1 + 8);
            __half2 h1c = *(const __half2*)(r1 + 16);
            __half2 h1d = *(const __half2*)(r1 + 24);
            if (RELU_IN) {
                h0a = __hmax2(h0a, zero2); h0b = __hmax2(h0b, zero2);
                h0c = __hmax2(h0c, zero2); h0d = __hmax2(h0d, zero2);
                h1a = __hmax2(h1a, zero2); h1b = __hmax2(h1b, zero2);
                h1c = __hmax2(h1c, zero2); h1d = __hmax2(h1d, zero2);
            }
            A0[0] = *reinterpret_cast<unsigned*>(&h0a);
            A0[1] = *reinterpret_cast<unsigned*>(&h1a);
            A0[2] = *reinterpret_cast<unsigned*>(&h0b);
            A0[3] = *reinterpret_cast<unsigned*>(&h1b);
            A1[0] = *reinterpret_cast<unsigned*>(&h0c);
            A1[1] = *reinterpret_cast<unsigned*>(&h1c);
            A1[2] = *reinterpret_cast<unsigned*>(&h0d);
            A1[3] = *reinterpret_cast<unsigned*>(&h1d);
        }

        float acc[20][4];
#pragma unroll
        for (int g = 0; g < 20; g++) {
            acc[g][0] = 0.f; acc[g][1] = 0.f; acc[g][2] = 0.f; acc[g][3] = 0.f;
        }
#pragma unroll
        for (int g = 0; g < 20; g++) {
            mma16816(acc[g], A0, bf[g][0]);
            mma16816(acc[g], A1, bf[g][1]);
        }

        // Messages: groups 0..15 -> hw fp16
        __half* hw0 = hw + (size_t)(m0 + row) * 128 + kq;
        __half* hw1 = hw0 + 8 * 128;
#pragma unroll
        for (int g = 0; g < 16; g++) {
            *reinterpret_cast<__half2*>(hw0 + 8 * g) = __floats2half2_rn(acc[g][0], acc[g][1]);
            *reinterpret_cast<__half2*>(hw1 + 8 * g) = __floats2half2_rn(acc[g][2], acc[g][3]);
        }
        // Self-loop + bias base: groups 16..19 -> agg fp16
        __half* ag0 = agg + (size_t)(m0 + row) * DD + kq;
        __half* ag1 = ag0 + 8 * DD;
#pragma unroll
        for (int gg = 0; gg < 4; gg++) {
            const int g = 16 + gg;
            *reinterpret_cast<__half2*>(ag0 + 8 * gg) =
                __floats2half2_rn(acc[g][0] + bvec[gg].x, acc[g][1] + bvec[gg].y);
            *reinterpret_cast<__half2*>(ag1 + 8 * gg) =
                __floats2half2_rn(acc[g][2] + bvec[gg].x, acc[g][3] + bvec[gg].y);
        }
    }
}

// ---------------------------------------------------------------------------
// edge kernel: agg[dst][:] += hw[src][etype][:]   (fp16 vector reductions)
// 4 lanes per edge; lane q handles 8 halves (16 B) via red.v4.f16x2.
// agg is 64 MB -> atomics stay L2-resident.
// ---------------------------------------------------------------------------
__global__ void edge_kernel(const __half* __restrict__ hw,
                            const int* __restrict__ src,
                            const int* __restrict__ dst,
                            const int* __restrict__ et,
                            __half* __restrict__ agg,
                            int E)
{
    int t = blockIdx.x * blockDim.x + threadIdx.x;
    int e = t >> 2;
    if (e >= E) return;
    int q = t & 3;

    int s = __ldg(src + e);
    int d = __ldg(dst + e);
    int r = __ldg(et + e);

    uint4 v = __ldg(reinterpret_cast<const uint4*>(hw + ((size_t)s * RR + r) * DD) + q);
    __half* p = agg + (size_t)d * DD + q * 8;
    asm volatile("red.global.add.noftz.v4.f16x2 [%0], {%1, %2, %3, %4};"
                 :: "l"(p), "r"(v.x), "r"(v.y), "r"(v.z), "r"(v.w)
                 : "memory");
}

// ---------------------------------------------------------------------------
// mean kernel: out[m][o] = mean_a relu(agg[m*32+a][o])
// ---------------------------------------------------------------------------
__global__ void mean_kernel(const __half* __restrict__ agg,
                            float* __restrict__ out, int M)
{
    int lane = threadIdx.x & 31;
    int m = (blockIdx.x * blockDim.x + threadIdx.x) >> 5;
    if (m >= M) return;
    float s = 0.0f;
#pragma unroll
    for (int a = 0; a < 32; a++)
        s += fmaxf(__half2float(agg[((size_t)m * 32 + a) * DD + lane]), 0.0f);
    out[(size_t)m * DD + lane] = s * (1.0f / 32.0f);
}

// ---------------------------------------------------------------------------
extern "C" void kernel_launch(void* const* d_in, const int* in_sizes, int n_in,
                              void* d_out, int out_size)
{
    const float* x    = (const float*)d_in[0];
    const float* W    = (const float*)d_in[1];
    const float* Wl   = (const float*)d_in[2];
    const float* bias = (const float*)d_in[3];
    const int*   src  = (const int*)d_in[4];
    const int*   dst  = (const int*)d_in[5];
    const int*   et   = (const int*)d_in[6];
    float* out = (float*)d_out;

    const int N = in_sizes[0] / DD;
    const int E = in_sizes[4];
    const int M = out_size / DD;
    const int nTiles = N / 16;

    void *hwP = nullptr, *aP = nullptr, *bP = nullptr;
    cudaGetSymbolAddress(&hwP, g_hw);
    cudaGetSymbolAddress(&aP, g_aggA);
    cudaGetSymbolAddress(&bP, g_aggB);
    __half* hwp  = (__half*)hwP;
    __half* aggA = (__half*)aP;
    __half* aggB = (__half*)bP;

    const int edgeBlocks = (E * 4 + 255) / 256;
    const int projBlocks = 1024;
    const int meanBlocks = (M * 32 + 255) / 256;

    // ---- Layer 1 ----
    proj_mma<false, float><<<projBlocks, 256>>>(x, W, Wl, bias, hwp, aggA, nTiles);
    edge_kernel<<<edgeBlocks, 256>>>(hwp, src, dst, et, aggA, E);

    // ---- Layer 2 (relu fused into fp16 A-load) ----
    proj_mma<true, __half><<<projBlocks, 256>>>(aggA, W, Wl, bias, hwp, aggB, nTiles);
    edge_kernel<<<edgeBlocks, 256>>>(hwp, src, dst, et, aggB, E);

    // ---- Per-molecule mean (relu fused) ----
    mean_kernel<<<meanBlocks, 256>>>(aggB, out, M);
}

// round 7
// speedup vs baseline: 1.7115x; 1.0339x over previous
#include <cuda_runtime.h>
#include <cuda_fp16.h>
#include <cstdint>

#define NMAX 1048576
#define EMAX 4194304
#define DD   32
#define RR   4

// Scratch (__device__ globals; no allocation allowed in kernel_launch)
__device__ __half g_h16[(size_t)NMAX * DD];   // 64 MB fp16 copy of layer-1 input
__device__ __half g_aggA[(size_t)NMAX * DD];  // 64 MB pre-activation layer 1
__device__ __half g_aggB[(size_t)NMAX * DD];  // 64 MB pre-activation layer 2

// ---------------------------------------------------------------------------
__device__ __forceinline__ unsigned pack_h2(float a, float b) {
    __half2 h = __floats2half2_rn(a, b);
    return *reinterpret_cast<unsigned*>(&h);
}
__device__ __forceinline__ unsigned h2u(__half2 v) {
    return *reinterpret_cast<unsigned*>(&v);
}

__device__ __forceinline__ void mma16816(float c[4], const unsigned a[4], const unsigned b[2]) {
    asm volatile("mma.sync.aligned.m16n8k16.row.col.f32.f16.f16.f32 "
                 "{%0,%1,%2,%3}, {%4,%5,%6,%7}, {%8,%9}, {%0,%1,%2,%3};"
                 : "+f"(c[0]), "+f"(c[1]), "+f"(c[2]), "+f"(c[3])
                 : "r"(a[0]), "r"(a[1]), "r"(a[2]), "r"(a[3]),
                   "r"(b[0]), "r"(b[1]));
}

// 4x4 transpose within a quad of lanes (elements are 32-bit half2 carriers).
// After: quad-lane j's element i = original quad-lane i's element j.
__device__ __forceinline__ void transpose4(unsigned v[4], int lane) {
    const int b0 = lane & 1;
    unsigned t0 = b0 ? v[0] : v[1];
    unsigned t1 = b0 ? v[2] : v[3];
    t0 = __shfl_xor_sync(0xffffffffu, t0, 1);
    t1 = __shfl_xor_sync(0xffffffffu, t1, 1);
    if (b0) { v[0] = t0; v[2] = t1; } else { v[1] = t0; v[3] = t1; }
    const int b1 = (lane >> 1) & 1;
    unsigned s0 = b1 ? v[0] : v[2];
    unsigned s1 = b1 ? v[1] : v[3];
    s0 = __shfl_xor_sync(0xffffffffu, s0, 2);
    s1 = __shfl_xor_sync(0xffffffffu, s1, 2);
    if (b1) { v[0] = s0; v[1] = s1; } else { v[2] = s0; v[3] = s1; }
}

// ---------------------------------------------------------------------------
// proj1: layer-1 self-loop.  aggA[n] = x[n]@Wl + bias (fp16), h16[n] = fp16(x[n]).
// Warp computes a [16 x 32] tile with 8 HMMA.
// ---------------------------------------------------------------------------
__global__ void __launch_bounds__(256)
proj1_kernel(const float* __restrict__ x,
             const float* __restrict__ Wl,
             const float* __restrict__ bias,
             __half* __restrict__ h16,
             __half* __restrict__ agg,
             int nTiles)
{
    const int lane   = threadIdx.x & 31;
    const int warpId = (blockIdx.x * blockDim.x + threadIdx.x) >> 5;
    const int nWarps = (gridDim.x * blockDim.x) >> 5;
    const int kq = 2 * (lane & 3);
    const int nq = lane >> 2;

    unsigned wf[4][2][2];
#pragma unroll
    for (int g = 0; g < 4; g++)
#pragma unroll
        for (int s = 0; s < 2; s++) {
            const int c  = 8 * g + nq;
            const int k0 = 16 * s + kq;
            wf[g][s][0] = pack_h2(__ldg(Wl + k0 * 32 + c),       __ldg(Wl + (k0 + 1) * 32 + c));
            wf[g][s][1] = pack_h2(__ldg(Wl + (k0 + 8) * 32 + c), __ldg(Wl + (k0 + 9) * 32 + c));
        }
    float2 bvec[4];
#pragma unroll
    for (int g = 0; g < 4; g++)
        bvec[g] = make_float2(__ldg(bias + kq + 8 * g), __ldg(bias + kq + 1 + 8 * g));

    for (int t = warpId; t < nTiles; t += nWarps) {
        const int m0 = t * 16;
        const float* r0 = x + (size_t)(m0 + nq) * DD + kq;
        const float* r1 = r0 + 8 * DD;
        float2 x0a = *(const float2*)(r0);
        float2 x0b = *(const float2*)(r0 + 8);
        float2 x0c = *(const float2*)(r0 + 16);
        float2 x0d = *(const float2*)(r0 + 24);
        float2 x1a = *(const float2*)(r1);
        float2 x1b = *(const float2*)(r1 + 8);
        float2 x1c = *(const float2*)(r1 + 16);
        float2 x1d = *(const float2*)(r1 + 24);

        unsigned A0[4] = { pack_h2(x0a.x, x0a.y), pack_h2(x1a.x, x1a.y),
                           pack_h2(x0b.x, x0b.y), pack_h2(x1b.x, x1b.y) };
        unsigned A1[4] = { pack_h2(x0c.x, x0c.y), pack_h2(x1c.x, x1c.y),
                           pack_h2(x0d.x, x0d.y), pack_h2(x1d.x, x1d.y) };

        float acc[4][4];
#pragma unroll
        for (int g = 0; g < 4; g++) {
            acc[g][0] = 0.f; acc[g][1] = 0.f; acc[g][2] = 0.f; acc[g][3] = 0.f;
        }
#pragma unroll
        for (int g = 0; g < 4; g++) {
            mma16816(acc[g], A0, wf[g][0]);
            mma16816(acc[g], A1, wf[g][1]);
        }

        // h16 = fp16(x): store this lane's A fragments back at their positions
        __half2* hr0 = reinterpret_cast<__half2*>(h16 + (size_t)(m0 + nq) * DD) + (kq >> 1);
        __half2* hr1 = reinterpret_cast<__half2*>(h16 + (size_t)(m0 + nq + 8) * DD) + (kq >> 1);
        hr0[0]  = *reinterpret_cast<__half2*>(&A0[0]);
        hr0[4]  = *reinterpret_cast<__half2*>(&A0[2]);
        hr0[8]  = *reinterpret_cast<__half2*>(&A1[0]);
        hr0[12] = *reinterpret_cast<__half2*>(&A1[2]);
        hr1[0]  = *reinterpret_cast<__half2*>(&A0[1]);
        hr1[4]  = *reinterpret_cast<__half2*>(&A0[3]);
        hr1[8]  = *reinterpret_cast<__half2*>(&A1[1]);
        hr1[12] = *reinterpret_cast<__half2*>(&A1[3]);

        __half* ag0 = agg + (size_t)(m0 + nq) * DD + kq;
        __half* ag1 = ag0 + 8 * DD;
#pragma unroll
        for (int g = 0; g < 4; g++) {
            *reinterpret_cast<__half2*>(ag0 + 8 * g) =
                __floats2half2_rn(acc[g][0] + bvec[g].x, acc[g][1] + bvec[g].y);
            *reinterpret_cast<__half2*>(ag1 + 8 * g) =
                __floats2half2_rn(acc[g][2] + bvec[g].x, acc[g][3] + bvec[g].y);
        }
    }
}

// ---------------------------------------------------------------------------
// proj2: layer-2 self-loop.  aggB[n] = relu(aggA[n])@Wl + bias (fp16 in/out).
// ---------------------------------------------------------------------------
__global__ void __launch_bounds__(256)
proj2_kernel(const __half* __restrict__ hin,
             const float* __restrict__ Wl,
             const float* __restrict__ bias,
             __half* __restrict__ agg,
             int nTiles)
{
    const int lane   = threadIdx.x & 31;
    const int warpId = (blockIdx.x * blockDim.x + threadIdx.x) >> 5;
    const int nWarps = (gridDim.x * blockDim.x) >> 5;
    const int kq = 2 * (lane & 3);
    const int nq = lane >> 2;

    unsigned wf[4][2][2];
#pragma unroll
    for (int g = 0; g < 4; g++)
#pragma unroll
        for (int s = 0; s < 2; s++) {
            const int c  = 8 * g + nq;
            const int k0 = 16 * s + kq;
            wf[g][s][0] = pack_h2(__ldg(Wl + k0 * 32 + c),       __ldg(Wl + (k0 + 1) * 32 + c));
            wf[g][s][1] = pack_h2(__ldg(Wl + (k0 + 8) * 32 + c), __ldg(Wl + (k0 + 9) * 32 + c));
        }
    float2 bvec[4];
#pragma unroll
    for (int g = 0; g < 4; g++)
        bvec[g] = make_float2(__ldg(bias + kq + 8 * g), __ldg(bias + kq + 1 + 8 * g));

    const __half2 z2 = __float2half2_rn(0.0f);

    for (int t = warpId; t < nTiles; t += nWarps) {
        const int m0 = t * 16;
        const __half2* r0 = reinterpret_cast<const __half2*>(hin + (size_t)(m0 + nq) * DD) + (kq >> 1);
        const __half2* r1 = reinterpret_cast<const __half2*>(hin + (size_t)(m0 + nq + 8) * DD) + (kq >> 1);

        unsigned A0[4] = { h2u(__hmax2(r0[0], z2)),  h2u(__hmax2(r1[0], z2)),
                           h2u(__hmax2(r0[4], z2)),  h2u(__hmax2(r1[4], z2)) };
        unsigned A1[4] = { h2u(__hmax2(r0[8], z2)),  h2u(__hmax2(r1[8], z2)),
                           h2u(__hmax2(r0[12], z2)), h2u(__hmax2(r1[12], z2)) };

        float acc[4][4];
#pragma unroll
        for (int g = 0; g < 4; g++) {
            acc[g][0] = 0.f; acc[g][1] = 0.f; acc[g][2] = 0.f; acc[g][3] = 0.f;
        }
#pragma unroll
        for (int g = 0; g < 4; g++) {
            mma16816(acc[g], A0, wf[g][0]);
            mma16816(acc[g], A1, wf[g][1]);
        }

        __half* ag0 = agg + (size_t)(m0 + nq) * DD + kq;
        __half* ag1 = ag0 + 8 * DD;
#pragma unroll
        for (int g = 0; g < 4; g++) {
            *reinterpret_cast<__half2*>(ag0 + 8 * g) =
                __floats2half2_rn(acc[g][0] + bvec[g].x, acc[g][1] + bvec[g].y);
            *reinterpret_cast<__half2*>(ag1 + 8 * g) =
                __floats2half2_rn(acc[g][2] + bvec[g].x, acc[g][3] + bvec[g].y);
        }
    }
}

// ---------------------------------------------------------------------------
// edge_mma: fused gather + projection + scatter.
// Per warp-tile of 16 edges:
//   A[i][:] = (relu?)(h[src[i]][:])  (fp16, gathered; L2-resident 64 MB array)
//   for r in 0..3: acc += maskA(etype==r) @ W_r  (masked HMMA)
//   transpose quads -> red.v4.f16x2 into agg[dst[i]]
// ---------------------------------------------------------------------------
template <bool RELU>
__global__ void __launch_bounds__(128)
edge_mma_kernel(const __half* __restrict__ h,
                const float* __restrict__ W,   // [4,32,32] f32
                const int* __restrict__ src,
                const int* __restrict__ dst,
                const int* __restrict__ et,
                __half* __restrict__ agg,
                int nTiles, int E)
{
    const int lane   = threadIdx.x & 31;
    const int warpId = (blockIdx.x * blockDim.x + threadIdx.x) >> 5;
    const int nWarps = (gridDim.x * blockDim.x) >> 5;
    const int kq = 2 * (lane & 3);
    const int nq = lane >> 2;

    // B fragments for all 4 relations: [r][g][s][j]
    unsigned bf[4][4][2][2];
#pragma unroll
    for (int r = 0; r < 4; r++)
#pragma unroll
        for (int g = 0; g < 4; g++)
#pragma unroll
            for (int s = 0; s < 2; s++) {
                const int c  = 8 * g + nq;
                const int k0 = 16 * s + kq;
                const float* Wr = W + r * 1024;
                bf[r][g][s][0] = pack_h2(__ldg(Wr + k0 * 32 + c),       __ldg(Wr + (k0 + 1) * 32 + c));
                bf[r][g][s][1] = pack_h2(__ldg(Wr + (k0 + 8) * 32 + c), __ldg(Wr + (k0 + 9) * 32 + c));
            }

    const __half2 z2 = __float2half2_rn(0.0f);

    for (int t = warpId; t < nTiles; t += nWarps) {
        const int e0 = t * 16;
        int sv = 0, ev = -1, dv = 0;
        const int mye = e0 + lane;
        if (lane < 16 && mye < E) {
            sv = __ldg(src + mye);
            ev = __ldg(et + mye);
            dv = __ldg(dst + mye);
        }
        const int sA = __shfl_sync(0xffffffffu, sv, nq);
        const int sB = __shfl_sync(0xffffffffu, sv, nq + 8);
        const int eA = __shfl_sync(0xffffffffu, ev, nq);
        const int eB = __shfl_sync(0xffffffffu, ev, nq + 8);

        const __half2* rA = reinterpret_cast<const __half2*>(h + (size_t)sA * DD) + (kq >> 1);
        const __half2* rB = reinterpret_cast<const __half2*>(h + (size_t)sB * DD) + (kq >> 1);
        __half2 a0 = __ldg(rA);      __half2 b0 = __ldg(rB);
        __half2 a1 = __ldg(rA + 4);  __half2 b1 = __ldg(rB + 4);
        __half2 a2 = __ldg(rA + 8);  __half2 b2 = __ldg(rB + 8);
        __half2 a3 = __ldg(rA + 12); __half2 b3 = __ldg(rB + 12);
        if (RELU) {
            a0 = __hmax2(a0, z2); a1 = __hmax2(a1, z2);
            a2 = __hmax2(a2, z2); a3 = __hmax2(a3, z2);
            b0 = __hmax2(b0, z2); b1 = __hmax2(b1, z2);
            b2 = __hmax2(b2, z2); b3 = __hmax2(b3, z2);
        }

        unsigned A0[4] = { h2u(a0), h2u(b0), h2u(a1), h2u(b1) };
        unsigned A1[4] = { h2u(a2), h2u(b2), h2u(a3), h2u(b3) };

        float acc[4][4];
#pragma unroll
        for (int g = 0; g < 4; g++) {
            acc[g][0] = 0.f; acc[g][1] = 0.f; acc[g][2] = 0.f; acc[g][3] = 0.f;
        }

#pragma unroll
        for (int r = 0; r < 4; r++) {
            const unsigned mA = (eA == r) ? 0xffffffffu : 0u;
            const unsigned mB = (eB == r) ? 0xffffffffu : 0u;
            unsigned Am0[4] = { A0[0] & mA, A0[1] & mB, A0[2] & mA, A0[3] & mB };
            unsigned Am1[4] = { A1[0] & mA, A1[1] & mB, A1[2] & mA, A1[3] & mB };
#pragma unroll
            for (int g = 0; g < 4; g++) {
                mma16816(acc[g], Am0, bf[r][g][0]);
                mma16816(acc[g], Am1, bf[r][g][1]);
            }
        }

        // Rows nq (Hn) and nq+8 (Hm): pack, transpose quads, RED 16 B per lane.
        unsigned Hn[4], Hm[4];
#pragma unroll
        for (int g = 0; g < 4; g++) {
            Hn[g] = pack_h2(acc[g][0], acc[g][1]);
            Hm[g] = pack_h2(acc[g][2], acc[g][3]);
        }
        transpose4(Hn, lane);
        transpose4(Hm, lane);

        const int dA = __shfl_sync(0xffffffffu, dv, nq);
        const int dB = __shfl_sync(0xffffffffu, dv, nq + 8);

        if (eA >= 0) {
            __half* p = agg + (size_t)dA * DD + (lane & 3) * 8;
            asm volatile("red.global.add.noftz.v4.f16x2 [%0], {%1, %2, %3, %4};"
                         :: "l"(p), "r"(Hn[0]), "r"(Hn[1]), "r"(Hn[2]), "r"(Hn[3])
                         : "memory");
        }
        if (eB >= 0) {
            __half* p = agg + (size_t)dB * DD + (lane & 3) * 8;
            asm volatile("red.global.add.noftz.v4.f16x2 [%0], {%1, %2, %3, %4};"
                         :: "l"(p), "r"(Hm[0]), "r"(Hm[1]), "r"(Hm[2]), "r"(Hm[3])
                         : "memory");
        }
    }
}

// ---------------------------------------------------------------------------
__global__ void mean_kernel(const __half* __restrict__ agg,
                            float* __restrict__ out, int M)
{
    int lane = threadIdx.x & 31;
    int m = (blockIdx.x * blockDim.x + threadIdx.x) >> 5;
    if (m >= M) return;
    float s = 0.0f;
#pragma unroll
    for (int a = 0; a < 32; a++)
        s += fmaxf(__half2float(agg[((size_t)m * 32 + a) * DD + lane]), 0.0f);
    out[(size_t)m * DD + lane] = s * (1.0f / 32.0f);
}

// ---------------------------------------------------------------------------
extern "C" void kernel_launch(void* const* d_in, const int* in_sizes, int n_in,
                              void* d_out, int out_size)
{
    const float* x    = (const float*)d_in[0];
    const float* W    = (const float*)d_in[1];
    const float* Wl   = (const float*)d_in[2];
    const float* bias = (const float*)d_in[3];
    const int*   src  = (const int*)d_in[4];
    const int*   dst  = (const int*)d_in[5];
    const int*   et   = (const int*)d_in[6];
    float* out = (float*)d_out;

    const int N = in_sizes[0] / DD;
    const int E = in_sizes[4];
    const int M = out_size / DD;
    const int nTilesN = N / 16;
    const int nTilesE = (E + 15) / 16;

    void *hP = nullptr, *aP = nullptr, *bP = nullptr;
    cudaGetSymbolAddress(&hP, g_h16);
    cudaGetSymbolAddress(&aP, g_aggA);
    cudaGetSymbolAddress(&bP, g_aggB);
    __half* h16  = (__half*)hP;
    __half* aggA = (__half*)aP;
    __half* aggB = (__half*)bP;

    const int projBlocks = 1024;   // 256 thr
    const int edgeBlocks = 2048;   // 128 thr
    const int meanBlocks = (M * 32 + 255) / 256;

    // ---- Layer 1 ----
    proj1_kernel<<<projBlocks, 256>>>(x, Wl, bias, h16, aggA, nTilesN);
    edge_mma_kernel<false><<<edgeBlocks, 128>>>(h16, W, src, dst, et, aggA, nTilesE, E);

    // ---- Layer 2 (gathers relu(aggA) directly; no intermediate h) ----
    proj2_kernel<<<projBlocks, 256>>>(aggA, Wl, bias, aggB, nTilesN);
    edge_mma_kernel<true><<<edgeBlocks, 128>>>(aggA, W, src, dst, et, aggB, nTilesE, E);

    // ---- Per-molecule mean (relu fused) ----
    mean_kernel<<<meanBlocks, 256>>>(aggB, out, M);
}

// round 8
// speedup vs baseline: 1.7116x; 1.0001x over previous
#include <cuda_runtime.h>
#include <cuda_fp16.h>
#include <cstdint>

#define NMAX 1048576
#define EMAX 4194304
#define DD   32
#define RR   4
#define HIST_CHUNK 4096
#define MAXBLK (EMAX / HIST_CHUNK)   // 1024

// Scratch (__device__ globals; no allocation allowed in kernel_launch)
__device__ __half g_h16[(size_t)NMAX * DD];          // 64 MB fp16 layer-1 input
__device__ __half g_aggA[(size_t)(NMAX + 16) * DD];  // 64 MB (+dummy rows)
__device__ __half g_aggB[(size_t)(NMAX + 16) * DD];  // 64 MB (+dummy rows)
__device__ int2   g_bedge[EMAX + 64];                // edges binned by etype: (src, dst)
__device__ int    g_bh[MAXBLK * RR];                 // per-block histograms
__device__ int    g_bb[MAXBLK * RR];                 // per-block scatter bases
__device__ int    g_meta[4];                         // s1, s2, s3, L(total, 16-aligned)

// ---------------------------------------------------------------------------
__device__ __forceinline__ unsigned pack_h2(float a, float b) {
    __half2 h = __floats2half2_rn(a, b);
    return *reinterpret_cast<unsigned*>(&h);
}
__device__ __forceinline__ unsigned h2u(__half2 v) {
    return *reinterpret_cast<unsigned*>(&v);
}

__device__ __forceinline__ void mma16816(float c[4], const unsigned a[4], const unsigned b[2]) {
    asm volatile("mma.sync.aligned.m16n8k16.row.col.f32.f16.f16.f32 "
                 "{%0,%1,%2,%3}, {%4,%5,%6,%7}, {%8,%9}, {%0,%1,%2,%3};"
                 : "+f"(c[0]), "+f"(c[1]), "+f"(c[2]), "+f"(c[3])
                 : "r"(a[0]), "r"(a[1]), "r"(a[2]), "r"(a[3]),
                   "r"(b[0]), "r"(b[1]));
}

// 4x4 transpose within a quad (32-bit half2 carriers).
__device__ __forceinline__ void transpose4(unsigned v[4], int lane) {
    const int b0 = lane & 1;
    unsigned t0 = b0 ? v[0] : v[1];
    unsigned t1 = b0 ? v[2] : v[3];
    t0 = __shfl_xor_sync(0xffffffffu, t0, 1);
    t1 = __shfl_xor_sync(0xffffffffu, t1, 1);
    if (b0) { v[0] = t0; v[2] = t1; } else { v[1] = t0; v[3] = t1; }
    const int b1 = (lane >> 1) & 1;
    unsigned s0 = b1 ? v[0] : v[2];
    unsigned s1 = b1 ? v[1] : v[3];
    s0 = __shfl_xor_sync(0xffffffffu, s0, 2);
    s1 = __shfl_xor_sync(0xffffffffu, s1, 2);
    if (b1) { v[0] = s0; v[1] = s1; } else { v[2] = s0; v[3] = s1; }
}

// ---------------------------------------------------------------------------
// Binning pass 1: per-block etype histogram (4096 edges / block)
// ---------------------------------------------------------------------------
__global__ void __launch_bounds__(256)
bin_hist_kernel(const int* __restrict__ et, int E)
{
    __shared__ int cnt[4];
    if (threadIdx.x < 4) cnt[threadIdx.x] = 0;
    __syncthreads();
    const int base = blockIdx.x * HIST_CHUNK;
#pragma unroll
    for (int i = 0; i < HIST_CHUNK / 256; i++) {
        int e = base + i * 256 + threadIdx.x;
        if (e < E) atomicAdd(&cnt[__ldg(et + e)], 1);
    }
    __syncthreads();
    if (threadIdx.x < 4) g_bh[blockIdx.x * 4 + threadIdx.x] = cnt[threadIdx.x];
}

// ---------------------------------------------------------------------------
// Binning pass 2: single-block scan over block histograms; compute 16-aligned
// bin starts, per-block bases, dummy fill, meta.
// ---------------------------------------------------------------------------
__device__ __forceinline__ int blk_exscan(int v, int* wsum, int tid, int* total) {
    const int lane = tid & 31, wid = tid >> 5;
    int x = v;
#pragma unroll
    for (int o = 1; o < 32; o <<= 1) {
        int y = __shfl_up_sync(0xffffffffu, x, o);
        if (lane >= o) x += y;
    }
    if (lane == 31) wsum[wid] = x;
    __syncthreads();
    if (tid < 32) {
        int s = wsum[tid];
        int t = s;
#pragma unroll
        for (int o = 1; o < 32; o <<= 1) {
            int y = __shfl_up_sync(0xffffffffu, t, o);
            if (tid >= o) t += y;
        }
        wsum[tid] = t - s;
        if (tid == 31) wsum[32] = t;   // grand total
    }
    __syncthreads();
    int r = x - v + wsum[wid];
    *total = wsum[32];
    __syncthreads();
    return r;
}

__global__ void __launch_bounds__(1024)
bin_scan_kernel(int nb, int N)
{
    __shared__ int wsum[33];
    const int tid = threadIdx.x;
    int ex[4], tot[4];
#pragma unroll
    for (int r = 0; r < 4; r++) {
        int v = (tid < nb) ? g_bh[tid * 4 + r] : 0;
        ex[r] = blk_exscan(v, wsum, tid, &tot[r]);
    }
    int start[5];
    start[0] = 0;
#pragma unroll
    for (int r = 0; r < 4; r++)
        start[r + 1] = (start[r] + tot[r] + 15) & ~15;

    if (tid < nb) {
#pragma unroll
        for (int r = 0; r < 4; r++)
            g_bb[tid * 4 + r] = start[r] + ex[r];
    }
    // Dummy fill of alignment gaps (dst = N -> spare agg row)
#pragma unroll
    for (int r = 0; r < 4; r++) {
        int gs = start[r] + tot[r];
        int i = gs + tid;
        if (i < start[r + 1]) g_bedge[i] = make_int2(0, N);
    }
    if (tid < 3) g_meta[tid] = start[tid + 1];
    if (tid == 3) g_meta[3] = start[4];
}

// ---------------------------------------------------------------------------
// Binning pass 3: scatter (src,dst) into bins via smem cursors
// ---------------------------------------------------------------------------
__global__ void __launch_bounds__(256)
bin_scatter_kernel(const int* __restrict__ src,
                   const int* __restrict__ dst,
                   const int* __restrict__ et, int E)
{
    __shared__ int cur[4];
    if (threadIdx.x < 4) cur[threadIdx.x] = g_bb[blockIdx.x * 4 + threadIdx.x];
    __syncthreads();
    const int base = blockIdx.x * HIST_CHUNK;
#pragma unroll
    for (int i = 0; i < HIST_CHUNK / 256; i++) {
        int e = base + i * 256 + threadIdx.x;
        if (e < E) {
            int r = __ldg(et + e);
            int pos = atomicAdd(&cur[r], 1);
            g_bedge[pos] = make_int2(__ldg(src + e), __ldg(dst + e));
        }
    }
}

// ---------------------------------------------------------------------------
// proj1: aggA[n] = x[n]@Wl + bias (fp16), h16[n] = fp16(x[n]).
// ---------------------------------------------------------------------------
__global__ void __launch_bounds__(256)
proj1_kernel(const float* __restrict__ x,
             const float* __restrict__ Wl,
             const float* __restrict__ bias,
             __half* __restrict__ h16,
             __half* __restrict__ agg,
             int nTiles)
{
    const int lane   = threadIdx.x & 31;
    const int warpId = (blockIdx.x * blockDim.x + threadIdx.x) >> 5;
    const int nWarps = (gridDim.x * blockDim.x) >> 5;
    const int kq = 2 * (lane & 3);
    const int nq = lane >> 2;

    unsigned wf[4][2][2];
#pragma unroll
    for (int g = 0; g < 4; g++)
#pragma unroll
        for (int s = 0; s < 2; s++) {
            const int c  = 8 * g + nq;
            const int k0 = 16 * s + kq;
            wf[g][s][0] = pack_h2(__ldg(Wl + k0 * 32 + c),       __ldg(Wl + (k0 + 1) * 32 + c));
            wf[g][s][1] = pack_h2(__ldg(Wl + (k0 + 8) * 32 + c), __ldg(Wl + (k0 + 9) * 32 + c));
        }
    float2 bvec[4];
#pragma unroll
    for (int g = 0; g < 4; g++)
        bvec[g] = make_float2(__ldg(bias + kq + 8 * g), __ldg(bias + kq + 1 + 8 * g));

    for (int t = warpId; t < nTiles; t += nWarps) {
        const int m0 = t * 16;
        const float* r0 = x + (size_t)(m0 + nq) * DD + kq;
        const float* r1 = r0 + 8 * DD;
        float2 x0a = *(const float2*)(r0);
        float2 x0b = *(const float2*)(r0 + 8);
        float2 x0c = *(const float2*)(r0 + 16);
        float2 x0d = *(const float2*)(r0 + 24);
        float2 x1a = *(const float2*)(r1);
        float2 x1b = *(const float2*)(r1 + 8);
        float2 x1c = *(const float2*)(r1 + 16);
        float2 x1d = *(const float2*)(r1 + 24);

        unsigned A0[4] = { pack_h2(x0a.x, x0a.y), pack_h2(x1a.x, x1a.y),
                           pack_h2(x0b.x, x0b.y), pack_h2(x1b.x, x1b.y) };
        unsigned A1[4] = { pack_h2(x0c.x, x0c.y), pack_h2(x1c.x, x1c.y),
                           pack_h2(x0d.x, x0d.y), pack_h2(x1d.x, x1d.y) };

        float acc[4][4];
#pragma unroll
        for (int g = 0; g < 4; g++) {
            acc[g][0] = 0.f; acc[g][1] = 0.f; acc[g][2] = 0.f; acc[g][3] = 0.f;
        }
#pragma unroll
        for (int g = 0; g < 4; g++) {
            mma16816(acc[g], A0, wf[g][0]);
            mma16816(acc[g], A1, wf[g][1]);
        }

        __half2* hr0 = reinterpret_cast<__half2*>(h16 + (size_t)(m0 + nq) * DD) + (kq >> 1);
        __half2* hr1 = reinterpret_cast<__half2*>(h16 + (size_t)(m0 + nq + 8) * DD) + (kq >> 1);
        hr0[0]  = *reinterpret_cast<__half2*>(&A0[0]);
        hr0[4]  = *reinterpret_cast<__half2*>(&A0[2]);
        hr0[8]  = *reinterpret_cast<__half2*>(&A1[0]);
        hr0[12] = *reinterpret_cast<__half2*>(&A1[2]);
        hr1[0]  = *reinterpret_cast<__half2*>(&A0[1]);
        hr1[4]  = *reinterpret_cast<__half2*>(&A0[3]);
        hr1[8]  = *reinterpret_cast<__half2*>(&A1[1]);
        hr1[12] = *reinterpret_cast<__half2*>(&A1[3]);

        __half* ag0 = agg + (size_t)(m0 + nq) * DD + kq;
        __half* ag1 = ag0 + 8 * DD;
#pragma unroll
        for (int g = 0; g < 4; g++) {
            *reinterpret_cast<__half2*>(ag0 + 8 * g) =
                __floats2half2_rn(acc[g][0] + bvec[g].x, acc[g][1] + bvec[g].y);
            *reinterpret_cast<__half2*>(ag1 + 8 * g) =
                __floats2half2_rn(acc[g][2] + bvec[g].x, acc[g][3] + bvec[g].y);
        }
    }
}

// ---------------------------------------------------------------------------
// proj2: aggB[n] = relu(aggA[n])@Wl + bias (fp16 in/out).
// ---------------------------------------------------------------------------
__global__ void __launch_bounds__(256)
proj2_kernel(const __half* __restrict__ hin,
             const float* __restrict__ Wl,
             const float* __restrict__ bias,
             __half* __restrict__ agg,
             int nTiles)
{
    const int lane   = threadIdx.x & 31;
    const int warpId = (blockIdx.x * blockDim.x + threadIdx.x) >> 5;
    const int nWarps = (gridDim.x * blockDim.x) >> 5;
    const int kq = 2 * (lane & 3);
    const int nq = lane >> 2;

    unsigned wf[4][2][2];
#pragma unroll
    for (int g = 0; g < 4; g++)
#pragma unroll
        for (int s = 0; s < 2; s++) {
            const int c  = 8 * g + nq;
            const int k0 = 16 * s + kq;
            wf[g][s][0] = pack_h2(__ldg(Wl + k0 * 32 + c),       __ldg(Wl + (k0 + 1) * 32 + c));
            wf[g][s][1] = pack_h2(__ldg(Wl + (k0 + 8) * 32 + c), __ldg(Wl + (k0 + 9) * 32 + c));
        }
    float2 bvec[4];
#pragma unroll
    for (int g = 0; g < 4; g++)
        bvec[g] = make_float2(__ldg(bias + kq + 8 * g), __ldg(bias + kq + 1 + 8 * g));

    const __half2 z2 = __float2half2_rn(0.0f);

    for (int t = warpId; t < nTiles; t += nWarps) {
        const int m0 = t * 16;
        const __half2* r0 = reinterpret_cast<const __half2*>(hin + (size_t)(m0 + nq) * DD) + (kq >> 1);
        const __half2* r1 = reinterpret_cast<const __half2*>(hin + (size_t)(m0 + nq + 8) * DD) + (kq >> 1);

        unsigned A0[4] = { h2u(__hmax2(r0[0], z2)),  h2u(__hmax2(r1[0], z2)),
                           h2u(__hmax2(r0[4], z2)),  h2u(__hmax2(r1[4], z2)) };
        unsigned A1[4] = { h2u(__hmax2(r0[8], z2)),  h2u(__hmax2(r1[8], z2)),
                           h2u(__hmax2(r0[12], z2)), h2u(__hmax2(r1[12], z2)) };

        float acc[4][4];
#pragma unroll
        for (int g = 0; g < 4; g++) {
            acc[g][0] = 0.f; acc[g][1] = 0.f; acc[g][2] = 0.f; acc[g][3] = 0.f;
        }
#pragma unroll
        for (int g = 0; g < 4; g++) {
            mma16816(acc[g], A0, wf[g][0]);
            mma16816(acc[g], A1, wf[g][1]);
        }

        __half* ag0 = agg + (size_t)(m0 + nq) * DD + kq;
        __half* ag1 = ag0 + 8 * DD;
#pragma unroll
        for (int g = 0; g < 4; g++) {
            *reinterpret_cast<__half2*>(ag0 + 8 * g) =
                __floats2half2_rn(acc[g][0] + bvec[g].x, acc[g][1] + bvec[g].y);
            *reinterpret_cast<__half2*>(ag1 + 8 * g) =
                __floats2half2_rn(acc[g][2] + bvec[g].x, acc[g][3] + bvec[g].y);
        }
    }
}

// ---------------------------------------------------------------------------
// edge_mma (binned): each 16-edge tile is single-relation -> 8 HMMA, no masks.
// ---------------------------------------------------------------------------
#define DO8(RSEL)                                                  \
    _Pragma("unroll")                                              \
    for (int g = 0; g < 4; g++) {                                  \
        mma16816(acc[g], A0, bf[RSEL][g][0]);                      \
        mma16816(acc[g], A1, bf[RSEL][g][1]);                      \
    }

template <bool RELU>
__global__ void __launch_bounds__(128)
edge_mma_kernel(const __half* __restrict__ h,
                const float* __restrict__ W,
                __half* __restrict__ agg)
{
    const int lane   = threadIdx.x & 31;
    const int warpId = (blockIdx.x * blockDim.x + threadIdx.x) >> 5;
    const int nWarps = (gridDim.x * blockDim.x) >> 5;
    const int kq = 2 * (lane & 3);
    const int nq = lane >> 2;

    unsigned bf[4][4][2][2];
#pragma unroll
    for (int r = 0; r < 4; r++)
#pragma unroll
        for (int g = 0; g < 4; g++)
#pragma unroll
            for (int s = 0; s < 2; s++) {
                const int c  = 8 * g + nq;
                const int k0 = 16 * s + kq;
                const float* Wr = W + r * 1024;
                bf[r][g][s][0] = pack_h2(__ldg(Wr + k0 * 32 + c),       __ldg(Wr + (k0 + 1) * 32 + c));
                bf[r][g][s][1] = pack_h2(__ldg(Wr + (k0 + 8) * 32 + c), __ldg(Wr + (k0 + 9) * 32 + c));
            }

    const int s1 = g_meta[0], s2 = g_meta[1], s3 = g_meta[2];
    const int nTiles = g_meta[3] >> 4;
    const __half2 z2 = __float2half2_rn(0.0f);

    for (int t = warpId; t < nTiles; t += nWarps) {
        const int t16 = t * 16;
        const int r = (t16 >= s1) + (t16 >= s2) + (t16 >= s3);

        int sv = 0, dv = 0;
        if (lane < 16) {
            int2 ed = __ldg(&g_bedge[t16 + lane]);
            sv = ed.x; dv = ed.y;
        }
        const int sA = __shfl_sync(0xffffffffu, sv, nq);
        const int sB = __shfl_sync(0xffffffffu, sv, nq + 8);

        const __half2* rA = reinterpret_cast<const __half2*>(h + (size_t)sA * DD) + (kq >> 1);
        const __half2* rB = reinterpret_cast<const __half2*>(h + (size_t)sB * DD) + (kq >> 1);
        __half2 a0 = __ldg(rA);      __half2 b0 = __ldg(rB);
        __half2 a1 = __ldg(rA + 4);  __half2 b1 = __ldg(rB + 4);
        __half2 a2 = __ldg(rA + 8);  __half2 b2 = __ldg(rB + 8);
        __half2 a3 = __ldg(rA + 12); __half2 b3 = __ldg(rB + 12);
        if (RELU) {
            a0 = __hmax2(a0, z2); a1 = __hmax2(a1, z2);
            a2 = __hmax2(a2, z2); a3 = __hmax2(a3, z2);
            b0 = __hmax2(b0, z2); b1 = __hmax2(b1, z2);
            b2 = __hmax2(b2, z2); b3 = __hmax2(b3, z2);
        }

        unsigned A0[4] = { h2u(a0), h2u(b0), h2u(a1), h2u(b1) };
        unsigned A1[4] = { h2u(a2), h2u(b2), h2u(a3), h2u(b3) };

        float acc[4][4];
#pragma unroll
        for (int g = 0; g < 4; g++) {
            acc[g][0] = 0.f; acc[g][1] = 0.f; acc[g][2] = 0.f; acc[g][3] = 0.f;
        }
        switch (r) {
            case 0: DO8(0); break;
            case 1: DO8(1); break;
            case 2: DO8(2); break;
            default: DO8(3); break;
        }

        unsigned Hn[4], Hm[4];
#pragma unroll
        for (int g = 0; g < 4; g++) {
            Hn[g] = pack_h2(acc[g][0], acc[g][1]);
            Hm[g] = pack_h2(acc[g][2], acc[g][3]);
        }
        transpose4(Hn, lane);
        transpose4(Hm, lane);

        const int dA = __shfl_sync(0xffffffffu, dv, nq);
        const int dB = __shfl_sync(0xffffffffu, dv, nq + 8);

        __half* pA = agg + (size_t)dA * DD + (lane & 3) * 8;
        asm volatile("red.global.add.noftz.v4.f16x2 [%0], {%1, %2, %3, %4};"
                     :: "l"(pA), "r"(Hn[0]), "r"(Hn[1]), "r"(Hn[2]), "r"(Hn[3])
                     : "memory");
        __half* pB = agg + (size_t)dB * DD + (lane & 3) * 8;
        asm volatile("red.global.add.noftz.v4.f16x2 [%0], {%1, %2, %3, %4};"
                     :: "l"(pB), "r"(Hm[0]), "r"(Hm[1]), "r"(Hm[2]), "r"(Hm[3])
                     : "memory");
    }
}

// ---------------------------------------------------------------------------
__global__ void mean_kernel(const __half* __restrict__ agg,
                            float* __restrict__ out, int M)
{
    int lane = threadIdx.x & 31;
    int m = (blockIdx.x * blockDim.x + threadIdx.x) >> 5;
    if (m >= M) return;
    float s = 0.0f;
#pragma unroll
    for (int a = 0; a < 32; a++)
        s += fmaxf(__half2float(agg[((size_t)m * 32 + a) * DD + lane]), 0.0f);
    out[(size_t)m * DD + lane] = s * (1.0f / 32.0f);
}

// ---------------------------------------------------------------------------
extern "C" void kernel_launch(void* const* d_in, const int* in_sizes, int n_in,
                              void* d_out, int out_size)
{
    const float* x    = (const float*)d_in[0];
    const float* W    = (const float*)d_in[1];
    const float* Wl   = (const float*)d_in[2];
    const float* bias = (const float*)d_in[3];
    const int*   src  = (const int*)d_in[4];
    const int*   dst  = (const int*)d_in[5];
    const int*   et   = (const int*)d_in[6];
    float* out = (float*)d_out;

    const int N = in_sizes[0] / DD;
    const int E = in_sizes[4];
    const int M = out_size / DD;
    const int nTilesN = N / 16;
    const int nb = (E + HIST_CHUNK - 1) / HIST_CHUNK;

    void *hP = nullptr, *aP = nullptr, *bP = nullptr;
    cudaGetSymbolAddress(&hP, g_h16);
    cudaGetSymbolAddress(&aP, g_aggA);
    cudaGetSymbolAddress(&bP, g_aggB);
    __half* h16  = (__half*)hP;
    __half* aggA = (__half*)aP;
    __half* aggB = (__half*)bP;

    const int projBlocks = 1024;
    const int edgeBlocks = 8192;
    const int meanBlocks = (M * 32 + 255) / 256;

    // ---- Bin edges by etype (once; reused by both layers) ----
    bin_hist_kernel<<<nb, 256>>>(et, E);
    bin_scan_kernel<<<1, 1024>>>(nb, N);
    bin_scatter_kernel<<<nb, 256>>>(src, dst, et, E);

    // ---- Layer 1 ----
    proj1_kernel<<<projBlocks, 256>>>(x, Wl, bias, h16, aggA, nTilesN);
    edge_mma_kernel<false><<<edgeBlocks, 128>>>(h16, W, aggA);

    // ---- Layer 2 (gathers relu(aggA) directly) ----
    proj2_kernel<<<projBlocks, 256>>>(aggA, Wl, bias, aggB, nTilesN);
    edge_mma_kernel<true><<<edgeBlocks, 128>>>(aggA, W, aggB);

    // ---- Per-molecule mean (relu fused) ----
    mean_kernel<<<meanBlocks, 256>>>(aggB, out, M);
}

// round 9
// speedup vs baseline: 2.2585x; 1.3196x over previous
#include <cuda_runtime.h>
#include <cuda_fp16.h>
#include <cstdint>

#define NMAX 1048576
#define EMAX 4194304
#define DD   32
#define RR   4
#define HIST_CHUNK 4096
#define MAXBLK (EMAX / HIST_CHUNK)   // 1024

// Scratch (__device__ globals; no allocation allowed in kernel_launch)
__device__ __half g_h16[(size_t)NMAX * DD];          // 64 MB fp16 layer-1 input
__device__ __half g_aggA[(size_t)(NMAX + 16) * DD];  // 64 MB (+dummy rows)
__device__ __half g_aggB[(size_t)(NMAX + 16) * DD];  // 64 MB (+dummy rows)
__device__ int2   g_bedge[EMAX + 64];                // edges binned by etype: (src, dst)
__device__ int    g_bh[MAXBLK * RR];                 // per-block histograms
__device__ int    g_bb[MAXBLK * RR];                 // per-block scatter bases
__device__ int    g_meta[4];                         // bin ends (16-aligned)

// ---------------------------------------------------------------------------
__device__ __forceinline__ unsigned pack_h2(float a, float b) {
    __half2 h = __floats2half2_rn(a, b);
    return *reinterpret_cast<unsigned*>(&h);
}
__device__ __forceinline__ unsigned h2u(__half2 v) {
    return *reinterpret_cast<unsigned*>(&v);
}

__device__ __forceinline__ void mma16816(float c[4], const unsigned a[4], const unsigned b[2]) {
    asm volatile("mma.sync.aligned.m16n8k16.row.col.f32.f16.f16.f32 "
                 "{%0,%1,%2,%3}, {%4,%5,%6,%7}, {%8,%9}, {%0,%1,%2,%3};"
                 : "+f"(c[0]), "+f"(c[1]), "+f"(c[2]), "+f"(c[3])
                 : "r"(a[0]), "r"(a[1]), "r"(a[2]), "r"(a[3]),
                   "r"(b[0]), "r"(b[1]));
}

// 4x4 transpose within a quad (32-bit half2 carriers).
__device__ __forceinline__ void transpose4(unsigned v[4], int lane) {
    const int b0 = lane & 1;
    unsigned t0 = b0 ? v[0] : v[1];
    unsigned t1 = b0 ? v[2] : v[3];
    t0 = __shfl_xor_sync(0xffffffffu, t0, 1);
    t1 = __shfl_xor_sync(0xffffffffu, t1, 1);
    if (b0) { v[0] = t0; v[2] = t1; } else { v[1] = t0; v[3] = t1; }
    const int b1 = (lane >> 1) & 1;
    unsigned s0 = b1 ? v[0] : v[2];
    unsigned s1 = b1 ? v[1] : v[3];
    s0 = __shfl_xor_sync(0xffffffffu, s0, 2);
    s1 = __shfl_xor_sync(0xffffffffu, s1, 2);
    if (b1) { v[0] = s0; v[1] = s1; } else { v[2] = s0; v[3] = s1; }
}

// ---------------------------------------------------------------------------
// Binning pass 1: per-block etype histogram (4096 edges / block)
// ---------------------------------------------------------------------------
__global__ void __launch_bounds__(256)
bin_hist_kernel(const int* __restrict__ et, int E)
{
    __shared__ int cnt[4];
    if (threadIdx.x < 4) cnt[threadIdx.x] = 0;
    __syncthreads();
    const int base = blockIdx.x * HIST_CHUNK;
#pragma unroll
    for (int i = 0; i < HIST_CHUNK / 256; i++) {
        int e = base + i * 256 + threadIdx.x;
        if (e < E) atomicAdd(&cnt[__ldg(et + e)], 1);
    }
    __syncthreads();
    if (threadIdx.x < 4) g_bh[blockIdx.x * 4 + threadIdx.x] = cnt[threadIdx.x];
}

// ---------------------------------------------------------------------------
// Binning pass 2: single-block scan; 16-aligned bin starts; dummy fill; meta.
// ---------------------------------------------------------------------------
__device__ __forceinline__ int blk_exscan(int v, int* wsum, int tid, int* total) {
    const int lane = tid & 31, wid = tid >> 5;
    int x = v;
#pragma unroll
    for (int o = 1; o < 32; o <<= 1) {
        int y = __shfl_up_sync(0xffffffffu, x, o);
        if (lane >= o) x += y;
    }
    if (lane == 31) wsum[wid] = x;
    __syncthreads();
    if (tid < 32) {
        int s = wsum[tid];
        int t = s;
#pragma unroll
        for (int o = 1; o < 32; o <<= 1) {
            int y = __shfl_up_sync(0xffffffffu, t, o);
            if (tid >= o) t += y;
        }
        wsum[tid] = t - s;
        if (tid == 31) wsum[32] = t;
    }
    __syncthreads();
    int r = x - v + wsum[wid];
    *total = wsum[32];
    __syncthreads();
    return r;
}

__global__ void __launch_bounds__(1024)
bin_scan_kernel(int nb, int N)
{
    __shared__ int wsum[33];
    const int tid = threadIdx.x;
    int ex[4], tot[4];
#pragma unroll
    for (int r = 0; r < 4; r++) {
        int v = (tid < nb) ? g_bh[tid * 4 + r] : 0;
        ex[r] = blk_exscan(v, wsum, tid, &tot[r]);
    }
    int start[5];
    start[0] = 0;
#pragma unroll
    for (int r = 0; r < 4; r++)
        start[r + 1] = (start[r] + tot[r] + 15) & ~15;

    if (tid < nb) {
#pragma unroll
        for (int r = 0; r < 4; r++)
            g_bb[tid * 4 + r] = start[r] + ex[r];
    }
#pragma unroll
    for (int r = 0; r < 4; r++) {
        int gs = start[r] + tot[r];
        int i = gs + tid;
        if (i < start[r + 1]) g_bedge[i] = make_int2(0, N);
    }
    if (tid < 4) g_meta[tid] = start[tid + 1];
}

// ---------------------------------------------------------------------------
// Binning pass 3: scatter (src,dst) via smem cursors
// ---------------------------------------------------------------------------
__global__ void __launch_bounds__(256)
bin_scatter_kernel(const int* __restrict__ src,
                   const int* __restrict__ dst,
                   const int* __restrict__ et, int E)
{
    __shared__ int cur[4];
    if (threadIdx.x < 4) cur[threadIdx.x] = g_bb[blockIdx.x * 4 + threadIdx.x];
    __syncthreads();
    const int base = blockIdx.x * HIST_CHUNK;
#pragma unroll
    for (int i = 0; i < HIST_CHUNK / 256; i++) {
        int e = base + i * 256 + threadIdx.x;
        if (e < E) {
            int r = __ldg(et + e);
            int pos = atomicAdd(&cur[r], 1);
            g_bedge[pos] = make_int2(__ldg(src + e), __ldg(dst + e));
        }
    }
}

// ---------------------------------------------------------------------------
// proj1: aggA[n] = x[n]@Wl + bias (fp16), h16[n] = fp16(x[n]).
// ---------------------------------------------------------------------------
__global__ void __launch_bounds__(256)
proj1_kernel(const float* __restrict__ x,
             const float* __restrict__ Wl,
             const float* __restrict__ bias,
             __half* __restrict__ h16,
             __half* __restrict__ agg,
             int nTiles)
{
    const int lane   = threadIdx.x & 31;
    const int warpId = (blockIdx.x * blockDim.x + threadIdx.x) >> 5;
    const int nWarps = (gridDim.x * blockDim.x) >> 5;
    const int kq = 2 * (lane & 3);
    const int nq = lane >> 2;

    unsigned wf[4][2][2];
#pragma unroll
    for (int g = 0; g < 4; g++)
#pragma unroll
        for (int s = 0; s < 2; s++) {
            const int c  = 8 * g + nq;
            const int k0 = 16 * s + kq;
            wf[g][s][0] = pack_h2(__ldg(Wl + k0 * 32 + c),       __ldg(Wl + (k0 + 1) * 32 + c));
            wf[g][s][1] = pack_h2(__ldg(Wl + (k0 + 8) * 32 + c), __ldg(Wl + (k0 + 9) * 32 + c));
        }
    float2 bvec[4];
#pragma unroll
    for (int g = 0; g < 4; g++)
        bvec[g] = make_float2(__ldg(bias + kq + 8 * g), __ldg(bias + kq + 1 + 8 * g));

    for (int t = warpId; t < nTiles; t += nWarps) {
        const int m0 = t * 16;
        const float* r0 = x + (size_t)(m0 + nq) * DD + kq;
        const float* r1 = r0 + 8 * DD;
        float2 x0a = *(const float2*)(r0);
        float2 x0b = *(const float2*)(r0 + 8);
        float2 x0c = *(const float2*)(r0 + 16);
        float2 x0d = *(const float2*)(r0 + 24);
        float2 x1a = *(const float2*)(r1);
        float2 x1b = *(const float2*)(r1 + 8);
        float2 x1c = *(const float2*)(r1 + 16);
        float2 x1d = *(const float2*)(r1 + 24);

        unsigned A0[4] = { pack_h2(x0a.x, x0a.y), pack_h2(x1a.x, x1a.y),
                           pack_h2(x0b.x, x0b.y), pack_h2(x1b.x, x1b.y) };
        unsigned A1[4] = { pack_h2(x0c.x, x0c.y), pack_h2(x1c.x, x1c.y),
                           pack_h2(x0d.x, x0d.y), pack_h2(x1d.x, x1d.y) };

        float acc[4][4];
#pragma unroll
        for (int g = 0; g < 4; g++) {
            acc[g][0] = 0.f; acc[g][1] = 0.f; acc[g][2] = 0.f; acc[g][3] = 0.f;
        }
#pragma unroll
        for (int g = 0; g < 4; g++) {
            mma16816(acc[g], A0, wf[g][0]);
            mma16816(acc[g], A1, wf[g][1]);
        }

        __half2* hr0 = reinterpret_cast<__half2*>(h16 + (size_t)(m0 + nq) * DD) + (kq >> 1);
        __half2* hr1 = reinterpret_cast<__half2*>(h16 + (size_t)(m0 + nq + 8) * DD) + (kq >> 1);
        hr0[0]  = *reinterpret_cast<__half2*>(&A0[0]);
        hr0[4]  = *reinterpret_cast<__half2*>(&A0[2]);
        hr0[8]  = *reinterpret_cast<__half2*>(&A1[0]);
        hr0[12] = *reinterpret_cast<__half2*>(&A1[2]);
        hr1[0]  = *reinterpret_cast<__half2*>(&A0[1]);
        hr1[4]  = *reinterpret_cast<__half2*>(&A0[3]);
        hr1[8]  = *reinterpret_cast<__half2*>(&A1[1]);
        hr1[12] = *reinterpret_cast<__half2*>(&A1[3]);

        __half* ag0 = agg + (size_t)(m0 + nq) * DD + kq;
        __half* ag1 = ag0 + 8 * DD;
#pragma unroll
        for (int g = 0; g < 4; g++) {
            *reinterpret_cast<__half2*>(ag0 + 8 * g) =
                __floats2half2_rn(acc[g][0] + bvec[g].x, acc[g][1] + bvec[g].y);
            *reinterpret_cast<__half2*>(ag1 + 8 * g) =
                __floats2half2_rn(acc[g][2] + bvec[g].x, acc[g][3] + bvec[g].y);
        }
    }
}

// ---------------------------------------------------------------------------
// proj2: aggB[n] = relu(aggA[n])@Wl + bias (fp16 in/out).
// ---------------------------------------------------------------------------
__global__ void __launch_bounds__(256)
proj2_kernel(const __half* __restrict__ hin,
             const float* __restrict__ Wl,
             const float* __restrict__ bias,
             __half* __restrict__ agg,
             int nTiles)
{
    const int lane   = threadIdx.x & 31;
    const int warpId = (blockIdx.x * blockDim.x + threadIdx.x) >> 5;
    const int nWarps = (gridDim.x * blockDim.x) >> 5;
    const int kq = 2 * (lane & 3);
    const int nq = lane >> 2;

    unsigned wf[4][2][2];
#pragma unroll
    for (int g = 0; g < 4; g++)
#pragma unroll
        for (int s = 0; s < 2; s++) {
            const int c  = 8 * g + nq;
            const int k0 = 16 * s + kq;
            wf[g][s][0] = pack_h2(__ldg(Wl + k0 * 32 + c),       __ldg(Wl + (k0 + 1) * 32 + c));
            wf[g][s][1] = pack_h2(__ldg(Wl + (k0 + 8) * 32 + c), __ldg(Wl + (k0 + 9) * 32 + c));
        }
    float2 bvec[4];
#pragma unroll
    for (int g = 0; g < 4; g++)
        bvec[g] = make_float2(__ldg(bias + kq + 8 * g), __ldg(bias + kq + 1 + 8 * g));

    const __half2 z2 = __float2half2_rn(0.0f);

    for (int t = warpId; t < nTiles; t += nWarps) {
        const int m0 = t * 16;
        const __half2* r0 = reinterpret_cast<const __half2*>(hin + (size_t)(m0 + nq) * DD) + (kq >> 1);
        const __half2* r1 = reinterpret_cast<const __half2*>(hin + (size_t)(m0 + nq + 8) * DD) + (kq >> 1);

        unsigned A0[4] = { h2u(__hmax2(r0[0], z2)),  h2u(__hmax2(r1[0], z2)),
                           h2u(__hmax2(r0[4], z2)),  h2u(__hmax2(r1[4], z2)) };
        unsigned A1[4] = { h2u(__hmax2(r0[8], z2)),  h2u(__hmax2(r1[8], z2)),
                           h2u(__hmax2(r0[12], z2)), h2u(__hmax2(r1[12], z2)) };

        float acc[4][4];
#pragma unroll
        for (int g = 0; g < 4; g++) {
            acc[g][0] = 0.f; acc[g][1] = 0.f; acc[g][2] = 0.f; acc[g][3] = 0.f;
        }
#pragma unroll
        for (int g = 0; g < 4; g++) {
            mma16816(acc[g], A0, wf[g][0]);
            mma16816(acc[g], A1, wf[g][1]);
        }

        __half* ag0 = agg + (size_t)(m0 + nq) * DD + kq;
        __half* ag1 = ag0 + 8 * DD;
#pragma unroll
        for (int g = 0; g < 4; g++) {
            *reinterpret_cast<__half2*>(ag0 + 8 * g) =
                __floats2half2_rn(acc[g][0] + bvec[g].x, acc[g][1] + bvec[g].y);
            *reinterpret_cast<__half2*>(ag1 + 8 * g) =
                __floats2half2_rn(acc[g][2] + bvec[g].x, acc[g][3] + bvec[g].y);
        }
    }
}

// ---------------------------------------------------------------------------
// edge_mma (per-relation template): only 8 B-frag regs; 2-stage software
// pipeline on the index + h-row gathers to double MLP.
// ---------------------------------------------------------------------------
template <int RSEL, bool RELU>
__global__ void __launch_bounds__(256)
edge_mma_kernel(const __half* __restrict__ h,
                const float* __restrict__ W,
                __half* __restrict__ agg)
{
    const int lane   = threadIdx.x & 31;
    const int warpId = (blockIdx.x * blockDim.x + threadIdx.x) >> 5;
    const int nWarps = (gridDim.x * blockDim.x) >> 5;
    const int kq = 2 * (lane & 3);
    const int nq = lane >> 2;

    // B fragments for this relation only (8 regs)
    unsigned bf[4][2][2];
    {
        const float* Wr = W + RSEL * 1024;
#pragma unroll
        for (int g = 0; g < 4; g++)
#pragma unroll
            for (int s = 0; s < 2; s++) {
                const int c  = 8 * g + nq;
                const int k0 = 16 * s + kq;
                bf[g][s][0] = pack_h2(__ldg(Wr + k0 * 32 + c),       __ldg(Wr + (k0 + 1) * 32 + c));
                bf[g][s][1] = pack_h2(__ldg(Wr + (k0 + 8) * 32 + c), __ldg(Wr + (k0 + 9) * 32 + c));
            }
    }

    const int tBeg = (RSEL == 0) ? 0 : (g_meta[RSEL - 1] >> 4);
    const int tEnd = g_meta[RSEL] >> 4;
    const __half2 z2 = __float2half2_rn(0.0f);

    int t = tBeg + warpId;
    if (t >= tEnd) return;

    // ---- Prologue: issue loads for tile t ----
    int sv = 0, dv = 0;
    if (lane < 16) {
        int2 ed = __ldg(&g_bedge[t * 16 + lane]);
        sv = ed.x; dv = ed.y;
    }
    int sA = __shfl_sync(0xffffffffu, sv, nq);
    int sB = __shfl_sync(0xffffffffu, sv, nq + 8);
    const __half2* rA = reinterpret_cast<const __half2*>(h + (size_t)sA * DD) + (kq >> 1);
    const __half2* rB = reinterpret_cast<const __half2*>(h + (size_t)sB * DD) + (kq >> 1);
    __half2 a0 = __ldg(rA);      __half2 b0 = __ldg(rB);
    __half2 a1 = __ldg(rA + 4);  __half2 b1 = __ldg(rB + 4);
    __half2 a2 = __ldg(rA + 8);  __half2 b2 = __ldg(rB + 8);
    __half2 a3 = __ldg(rA + 12); __half2 b3 = __ldg(rB + 12);

    for (; t < tEnd; ) {
        const int tn = t + nWarps;
        // ---- Issue next tile's loads before computing current ----
        int nsv = 0, ndv = 0;
        if (tn < tEnd && lane < 16) {
            int2 ed = __ldg(&g_bedge[tn * 16 + lane]);
            nsv = ed.x; ndv = ed.y;
        }
        const int nsA = __shfl_sync(0xffffffffu, nsv, nq);
        const int nsB = __shfl_sync(0xffffffffu, nsv, nq + 8);
        __half2 na0, na1, na2, na3, nb0, nb1, nb2, nb3;
        if (tn < tEnd) {
            const __half2* nrA = reinterpret_cast<const __half2*>(h + (size_t)nsA * DD) + (kq >> 1);
            const __half2* nrB = reinterpret_cast<const __half2*>(h + (size_t)nsB * DD) + (kq >> 1);
            na0 = __ldg(nrA);      nb0 = __ldg(nrB);
            na1 = __ldg(nrA + 4);  nb1 = __ldg(nrB + 4);
            na2 = __ldg(nrA + 8);  nb2 = __ldg(nrB + 8);
            na3 = __ldg(nrA + 12); nb3 = __ldg(nrB + 12);
        }

        // ---- Compute current tile ----
        if (RELU) {
            a0 = __hmax2(a0, z2); a1 = __hmax2(a1, z2);
            a2 = __hmax2(a2, z2); a3 = __hmax2(a3, z2);
            b0 = __hmax2(b0, z2); b1 = __hmax2(b1, z2);
            b2 = __hmax2(b2, z2); b3 = __hmax2(b3, z2);
        }
        unsigned A0[4] = { h2u(a0), h2u(b0), h2u(a1), h2u(b1) };
        unsigned A1[4] = { h2u(a2), h2u(b2), h2u(a3), h2u(b3) };

        float acc[4][4];
#pragma unroll
        for (int g = 0; g < 4; g++) {
            acc[g][0] = 0.f; acc[g][1] = 0.f; acc[g][2] = 0.f; acc[g][3] = 0.f;
        }
#pragma unroll
        for (int g = 0; g < 4; g++) {
            mma16816(acc[g], A0, bf[g][0]);
            mma16816(acc[g], A1, bf[g][1]);
        }

        unsigned Hn[4], Hm[4];
#pragma unroll
        for (int g = 0; g < 4; g++) {
            Hn[g] = pack_h2(acc[g][0], acc[g][1]);
            Hm[g] = pack_h2(acc[g][2], acc[g][3]);
        }
        transpose4(Hn, lane);
        transpose4(Hm, lane);

        const int dA = __shfl_sync(0xffffffffu, dv, nq);
        const int dB = __shfl_sync(0xffffffffu, dv, nq + 8);

        __half* pA = agg + (size_t)dA * DD + (lane & 3) * 8;
        asm volatile("red.global.add.noftz.v4.f16x2 [%0], {%1, %2, %3, %4};"
                     :: "l"(pA), "r"(Hn[0]), "r"(Hn[1]), "r"(Hn[2]), "r"(Hn[3])
                     : "memory");
        __half* pB = agg + (size_t)dB * DD + (lane & 3) * 8;
        asm volatile("red.global.add.noftz.v4.f16x2 [%0], {%1, %2, %3, %4};"
                     :: "l"(pB), "r"(Hm[0]), "r"(Hm[1]), "r"(Hm[2]), "r"(Hm[3])
                     : "memory");

        // ---- Rotate pipeline ----
        t = tn;
        sv = nsv; dv = ndv;
        a0 = na0; a1 = na1; a2 = na2; a3 = na3;
        b0 = nb0; b1 = nb1; b2 = nb2; b3 = nb3;
    }
}

// ---------------------------------------------------------------------------
__global__ void mean_kernel(const __half* __restrict__ agg,
                            float* __restrict__ out, int M)
{
    int lane = threadIdx.x & 31;
    int m = (blockIdx.x * blockDim.x + threadIdx.x) >> 5;
    if (m >= M) return;
    float s = 0.0f;
#pragma unroll
    for (int a = 0; a < 32; a++)
        s += fmaxf(__half2float(agg[((size_t)m * 32 + a) * DD + lane]), 0.0f);
    out[(size_t)m * DD + lane] = s * (1.0f / 32.0f);
}

// ---------------------------------------------------------------------------
extern "C" void kernel_launch(void* const* d_in, const int* in_sizes, int n_in,
                              void* d_out, int out_size)
{
    const float* x    = (const float*)d_in[0];
    const float* W    = (const float*)d_in[1];
    const float* Wl   = (const float*)d_in[2];
    const float* bias = (const float*)d_in[3];
    const int*   src  = (const int*)d_in[4];
    const int*   dst  = (const int*)d_in[5];
    const int*   et   = (const int*)d_in[6];
    float* out = (float*)d_out;

    const int N = in_sizes[0] / DD;
    const int E = in_sizes[4];
    const int M = out_size / DD;
    const int nTilesN = N / 16;
    const int nb = (E + HIST_CHUNK - 1) / HIST_CHUNK;

    void *hP = nullptr, *aP = nullptr, *bP = nullptr;
    cudaGetSymbolAddress(&hP, g_h16);
    cudaGetSymbolAddress(&aP, g_aggA);
    cudaGetSymbolAddress(&bP, g_aggB);
    __half* h16  = (__half*)hP;
    __half* aggA = (__half*)aP;
    __half* aggB = (__half*)bP;

    const int projBlocks = 1024;
    const int edgeBlocks = 2048;   // per relation, 256 thr = 16K warps
    const int meanBlocks = (M * 32 + 255) / 256;

    // ---- Bin edges by etype (once; reused by both layers) ----
    bin_hist_kernel<<<nb, 256>>>(et, E);
    bin_scan_kernel<<<1, 1024>>>(nb, N);
    bin_scatter_kernel<<<nb, 256>>>(src, dst, et, E);

    // ---- Layer 1 ----
    proj1_kernel<<<projBlocks, 256>>>(x, Wl, bias, h16, aggA, nTilesN);
    edge_mma_kernel<0, false><<<edgeBlocks, 256>>>(h16, W, aggA);
    edge_mma_kernel<1, false><<<edgeBlocks, 256>>>(h16, W, aggA);
    edge_mma_kernel<2, false><<<edgeBlocks, 256>>>(h16, W, aggA);
    edge_mma_kernel<3, false><<<edgeBlocks, 256>>>(h16, W, aggA);

    // ---- Layer 2 (gathers relu(aggA) directly) ----
    proj2_kernel<<<projBlocks, 256>>>(aggA, Wl, bias, aggB, nTilesN);
    edge_mma_kernel<0, true><<<edgeBlocks, 256>>>(aggA, W, aggB);
    edge_mma_kernel<1, true><<<edgeBlocks, 256>>>(aggA, W, aggB);
    edge_mma_kernel<2, true><<<edgeBlocks, 256>>>(aggA, W, aggB);
    edge_mma_kernel<3, true><<<edgeBlocks, 256>>>(aggA, W, aggB);

    // ---- Per-molecule mean (relu fused) ----
    mean_kernel<<<meanBlocks, 256>>>(aggB, out, M);
}

// round 10
// speedup vs baseline: 2.5628x; 1.1347x over previous
#include <cuda_runtime.h>
#include <cuda_fp16.h>
#include <cstdint>

#define NMAX 1048576
#define EMAX 4194304
#define DD   32
#define RR   4
#define HIST_CHUNK 4096
#define MAXBLK (EMAX / HIST_CHUNK)   // 1024

// Node feature arrays use "layout L": within a 32-half row, position
// j = 8q + 2m + odd holds feature f = 2q + 8m + odd  (q,m in 0..3).
// This makes MMA A-fragment loads AND accumulator scatters contiguous 16B.
__device__ __half g_h16[(size_t)NMAX * DD];          // 64 MB layer-1 input (layout L)
__device__ __half g_aggA[(size_t)(NMAX + 16) * DD];  // 64 MB (+dummy rows, layout L)
__device__ __half g_aggB[(size_t)(NMAX + 16) * DD];  // 64 MB (+dummy rows, layout L)
__device__ int2   g_bedge[EMAX + 64];                // edges binned by etype: (src, dst)
__device__ int    g_bh[MAXBLK * RR];
__device__ int    g_bb[MAXBLK * RR];
__device__ int    g_meta[4];                         // bin ends (16-aligned)

// ---------------------------------------------------------------------------
__device__ __forceinline__ unsigned pack_h2(float a, float b) {
    __half2 h = __floats2half2_rn(a, b);
    return *reinterpret_cast<unsigned*>(&h);
}
__device__ __forceinline__ unsigned relu_u(unsigned v) {
    __half2 h = *reinterpret_cast<__half2*>(&v);
    h = __hmax2(h, __float2half2_rn(0.0f));
    return *reinterpret_cast<unsigned*>(&h);
}

__device__ __forceinline__ void mma16816(float c[4], const unsigned a[4], const unsigned b[2]) {
    asm volatile("mma.sync.aligned.m16n8k16.row.col.f32.f16.f16.f32 "
                 "{%0,%1,%2,%3}, {%4,%5,%6,%7}, {%8,%9}, {%0,%1,%2,%3};"
                 : "+f"(c[0]), "+f"(c[1]), "+f"(c[2]), "+f"(c[3])
                 : "r"(a[0]), "r"(a[1]), "r"(a[2]), "r"(a[3]),
                   "r"(b[0]), "r"(b[1]));
}

// ---------------------------------------------------------------------------
// Binning pass 1: per-block etype histogram
// ---------------------------------------------------------------------------
__global__ void __launch_bounds__(256)
bin_hist_kernel(const int* __restrict__ et, int E)
{
    __shared__ int cnt[4];
    if (threadIdx.x < 4) cnt[threadIdx.x] = 0;
    __syncthreads();
    const int base = blockIdx.x * HIST_CHUNK;
#pragma unroll
    for (int i = 0; i < HIST_CHUNK / 256; i++) {
        int e = base + i * 256 + threadIdx.x;
        if (e < E) atomicAdd(&cnt[__ldg(et + e)], 1);
    }
    __syncthreads();
    if (threadIdx.x < 4) g_bh[blockIdx.x * 4 + threadIdx.x] = cnt[threadIdx.x];
}

// ---------------------------------------------------------------------------
// Binning pass 2: single-block scan; 16-aligned bin starts; dummy fill; meta.
// ---------------------------------------------------------------------------
__device__ __forceinline__ int blk_exscan(int v, int* wsum, int tid, int* total) {
    const int lane = tid & 31, wid = tid >> 5;
    int x = v;
#pragma unroll
    for (int o = 1; o < 32; o <<= 1) {
        int y = __shfl_up_sync(0xffffffffu, x, o);
        if (lane >= o) x += y;
    }
    if (lane == 31) wsum[wid] = x;
    __syncthreads();
    if (tid < 32) {
        int s = wsum[tid];
        int t = s;
#pragma unroll
        for (int o = 1; o < 32; o <<= 1) {
            int y = __shfl_up_sync(0xffffffffu, t, o);
            if (tid >= o) t += y;
        }
        wsum[tid] = t - s;
        if (tid == 31) wsum[32] = t;
    }
    __syncthreads();
    int r = x - v + wsum[wid];
    *total = wsum[32];
    __syncthreads();
    return r;
}

__global__ void __launch_bounds__(1024)
bin_scan_kernel(int nb, int N)
{
    __shared__ int wsum[33];
    const int tid = threadIdx.x;
    int ex[4], tot[4];
#pragma unroll
    for (int r = 0; r < 4; r++) {
        int v = (tid < nb) ? g_bh[tid * 4 + r] : 0;
        ex[r] = blk_exscan(v, wsum, tid, &tot[r]);
    }
    int start[5];
    start[0] = 0;
#pragma unroll
    for (int r = 0; r < 4; r++)
        start[r + 1] = (start[r] + tot[r] + 15) & ~15;

    if (tid < nb) {
#pragma unroll
        for (int r = 0; r < 4; r++)
            g_bb[tid * 4 + r] = start[r] + ex[r];
    }
#pragma unroll
    for (int r = 0; r < 4; r++) {
        int gs = start[r] + tot[r];
        int i = gs + tid;
        if (i < start[r + 1]) g_bedge[i] = make_int2(0, N);
    }
    if (tid < 4) g_meta[tid] = start[tid + 1];
}

// ---------------------------------------------------------------------------
// Binning pass 3: scatter (src,dst) via smem cursors
// ---------------------------------------------------------------------------
__global__ void __launch_bounds__(256)
bin_scatter_kernel(const int* __restrict__ src,
                   const int* __restrict__ dst,
                   const int* __restrict__ et, int E)
{
    __shared__ int cur[4];
    if (threadIdx.x < 4) cur[threadIdx.x] = g_bb[blockIdx.x * 4 + threadIdx.x];
    __syncthreads();
    const int base = blockIdx.x * HIST_CHUNK;
#pragma unroll
    for (int i = 0; i < HIST_CHUNK / 256; i++) {
        int e = base + i * 256 + threadIdx.x;
        if (e < E) {
            int r = __ldg(et + e);
            int pos = atomicAdd(&cur[r], 1);
            g_bedge[pos] = make_int2(__ldg(src + e), __ldg(dst + e));
        }
    }
}

// ---------------------------------------------------------------------------
// proj1: aggA[n] = x[n]@Wl + bias (layout L), h16[n] = fp16(x[n]) (layout L).
// Warp computes [16 x 32] with 8 HMMA. x is f32 standard layout.
// ---------------------------------------------------------------------------
__global__ void __launch_bounds__(256)
proj1_kernel(const float* __restrict__ x,
             const float* __restrict__ Wl,
             const float* __restrict__ bias,
             __half* __restrict__ h16,
             __half* __restrict__ agg,
             int nTiles)
{
    const int lane   = threadIdx.x & 31;
    const int warpId = (blockIdx.x * blockDim.x + threadIdx.x) >> 5;
    const int nWarps = (gridDim.x * blockDim.x) >> 5;
    const int kq = 2 * (lane & 3);
    const int nq = lane >> 2;
    const int p  = lane & 3;

    unsigned wf[4][2][2];
#pragma unroll
    for (int g = 0; g < 4; g++)
#pragma unroll
        for (int s = 0; s < 2; s++) {
            const int c  = 8 * g + nq;
            const int k0 = 16 * s + kq;
            wf[g][s][0] = pack_h2(__ldg(Wl + k0 * 32 + c),       __ldg(Wl + (k0 + 1) * 32 + c));
            wf[g][s][1] = pack_h2(__ldg(Wl + (k0 + 8) * 32 + c), __ldg(Wl + (k0 + 9) * 32 + c));
        }
    float2 bvec[4];
#pragma unroll
    for (int g = 0; g < 4; g++)
        bvec[g] = make_float2(__ldg(bias + kq + 8 * g), __ldg(bias + kq + 1 + 8 * g));

    for (int t = warpId; t < nTiles; t += nWarps) {
        const int m0 = t * 16;
        const float* r0 = x + (size_t)(m0 + nq) * DD + kq;
        const float* r1 = r0 + 8 * DD;
        float2 x0a = *(const float2*)(r0);
        float2 x0b = *(const float2*)(r0 + 8);
        float2 x0c = *(const float2*)(r0 + 16);
        float2 x0d = *(const float2*)(r0 + 24);
        float2 x1a = *(const float2*)(r1);
        float2 x1b = *(const float2*)(r1 + 8);
        float2 x1c = *(const float2*)(r1 + 16);
        float2 x1d = *(const float2*)(r1 + 24);

        unsigned A0[4] = { pack_h2(x0a.x, x0a.y), pack_h2(x1a.x, x1a.y),
                           pack_h2(x0b.x, x0b.y), pack_h2(x1b.x, x1b.y) };
        unsigned A1[4] = { pack_h2(x0c.x, x0c.y), pack_h2(x1c.x, x1c.y),
                           pack_h2(x0d.x, x0d.y), pack_h2(x1d.x, x1d.y) };

        float acc[4][4];
#pragma unroll
        for (int g = 0; g < 4; g++) {
            acc[g][0] = 0.f; acc[g][1] = 0.f; acc[g][2] = 0.f; acc[g][3] = 0.f;
        }
#pragma unroll
        for (int g = 0; g < 4; g++) {
            mma16816(acc[g], A0, wf[g][0]);
            mma16816(acc[g], A1, wf[g][1]);
        }

        // h16 rows in layout L: lane's 4 k-pair half2s are contiguous at 8p halves
        *reinterpret_cast<uint4*>(h16 + (size_t)(m0 + nq) * DD + 8 * p) =
            make_uint4(A0[0], A0[2], A1[0], A1[2]);
        *reinterpret_cast<uint4*>(h16 + (size_t)(m0 + nq + 8) * DD + 8 * p) =
            make_uint4(A0[1], A0[3], A1[1], A1[3]);

        // agg rows in layout L: o-pair (8g+2p) -> position 8p+2g (contiguous in g)
        *reinterpret_cast<uint4*>(agg + (size_t)(m0 + nq) * DD + 8 * p) =
            make_uint4(pack_h2(acc[0][0] + bvec[0].x, acc[0][1] + bvec[0].y),
                       pack_h2(acc[1][0] + bvec[1].x, acc[1][1] + bvec[1].y),
                       pack_h2(acc[2][0] + bvec[2].x, acc[2][1] + bvec[2].y),
                       pack_h2(acc[3][0] + bvec[3].x, acc[3][1] + bvec[3].y));
        *reinterpret_cast<uint4*>(agg + (size_t)(m0 + nq + 8) * DD + 8 * p) =
            make_uint4(pack_h2(acc[0][2] + bvec[0].x, acc[0][3] + bvec[0].y),
                       pack_h2(acc[1][2] + bvec[1].x, acc[1][3] + bvec[1].y),
                       pack_h2(acc[2][2] + bvec[2].x, acc[2][3] + bvec[2].y),
                       pack_h2(acc[3][2] + bvec[3].x, acc[3][3] + bvec[3].y));
    }
}

// ---------------------------------------------------------------------------
// proj2: aggB[n] = relu(aggA[n])@Wl + bias (both layout L).
// ---------------------------------------------------------------------------
__global__ void __launch_bounds__(256)
proj2_kernel(const __half* __restrict__ hin,
             const float* __restrict__ Wl,
             const float* __restrict__ bias,
             __half* __restrict__ agg,
             int nTiles)
{
    const int lane   = threadIdx.x & 31;
    const int warpId = (blockIdx.x * blockDim.x + threadIdx.x) >> 5;
    const int nWarps = (gridDim.x * blockDim.x) >> 5;
    const int kq = 2 * (lane & 3);
    const int nq = lane >> 2;
    const int p  = lane & 3;

    unsigned wf[4][2][2];
#pragma unroll
    for (int g = 0; g < 4; g++)
#pragma unroll
        for (int s = 0; s < 2; s++) {
            const int c  = 8 * g + nq;
            const int k0 = 16 * s + kq;
            wf[g][s][0] = pack_h2(__ldg(Wl + k0 * 32 + c),       __ldg(Wl + (k0 + 1) * 32 + c));
            wf[g][s][1] = pack_h2(__ldg(Wl + (k0 + 8) * 32 + c), __ldg(Wl + (k0 + 9) * 32 + c));
        }
    float2 bvec[4];
#pragma unroll
    for (int g = 0; g < 4; g++)
        bvec[g] = make_float2(__ldg(bias + kq + 8 * g), __ldg(bias + kq + 1 + 8 * g));

    for (int t = warpId; t < nTiles; t += nWarps) {
        const int m0 = t * 16;
        uint4 uA = *reinterpret_cast<const uint4*>(hin + (size_t)(m0 + nq) * DD + 8 * p);
        uint4 uB = *reinterpret_cast<const uint4*>(hin + (size_t)(m0 + nq + 8) * DD + 8 * p);

        unsigned A0[4] = { relu_u(uA.x), relu_u(uB.x), relu_u(uA.y), relu_u(uB.y) };
        unsigned A1[4] = { relu_u(uA.z), relu_u(uB.z), relu_u(uA.w), relu_u(uB.w) };

        float acc[4][4];
#pragma unroll
        for (int g = 0; g < 4; g++) {
            acc[g][0] = 0.f; acc[g][1] = 0.f; acc[g][2] = 0.f; acc[g][3] = 0.f;
        }
#pragma unroll
        for (int g = 0; g < 4; g++) {
            mma16816(acc[g], A0, wf[g][0]);
            mma16816(acc[g], A1, wf[g][1]);
        }

        *reinterpret_cast<uint4*>(agg + (size_t)(m0 + nq) * DD + 8 * p) =
            make_uint4(pack_h2(acc[0][0] + bvec[0].x, acc[0][1] + bvec[0].y),
                       pack_h2(acc[1][0] + bvec[1].x, acc[1][1] + bvec[1].y),
                       pack_h2(acc[2][0] + bvec[2].x, acc[2][1] + bvec[2].y),
                       pack_h2(acc[3][0] + bvec[3].x, acc[3][1] + bvec[3].y));
        *reinterpret_cast<uint4*>(agg + (size_t)(m0 + nq + 8) * DD + 8 * p) =
            make_uint4(pack_h2(acc[0][2] + bvec[0].x, acc[0][3] + bvec[0].y),
                       pack_h2(acc[1][2] + bvec[1].x, acc[1][3] + bvec[1].y),
                       pack_h2(acc[2][2] + bvec[2].x, acc[2][3] + bvec[2].y),
                       pack_h2(acc[3][2] + bvec[3].x, acc[3][3] + bvec[3].y));
    }
}

// ---------------------------------------------------------------------------
// edge_mma (merged, layout L): one launch covers all 4 relation bins.
// Block quarter -> relation. Per tile: 1 uint4 gather per lane per row-set,
// 8 HMMA, direct uint4 REDs (no transpose). 2-stage pipeline.
// ---------------------------------------------------------------------------
template <bool RELU>
__global__ void __launch_bounds__(256)
edge_mma_kernel(const __half* __restrict__ h,
                const float* __restrict__ W,
                __half* __restrict__ agg)
{
    const int lane = threadIdx.x & 31;
    const int kq = 2 * (lane & 3);
    const int nq = lane >> 2;
    const int p  = lane & 3;

    const int blocksPerRel = gridDim.x >> 2;
    const int r = blockIdx.x / blocksPerRel;
    const int warpInQ = (blockIdx.x % blocksPerRel) * (blockDim.x >> 5) + (threadIdx.x >> 5);
    const int qWarps  = blocksPerRel * (blockDim.x >> 5);

    // B fragments for this block's relation only (8 regs)
    unsigned bf[4][2][2];
    {
        const float* Wr = W + r * 1024;
#pragma unroll
        for (int g = 0; g < 4; g++)
#pragma unroll
            for (int s = 0; s < 2; s++) {
                const int c  = 8 * g + nq;
                const int k0 = 16 * s + kq;
                bf[g][s][0] = pack_h2(__ldg(Wr + k0 * 32 + c),       __ldg(Wr + (k0 + 1) * 32 + c));
                bf[g][s][1] = pack_h2(__ldg(Wr + (k0 + 8) * 32 + c), __ldg(Wr + (k0 + 9) * 32 + c));
            }
    }

    const int tBeg = (r == 0) ? 0 : (g_meta[r - 1] >> 4);
    const int tEnd = g_meta[r] >> 4;

    int t = tBeg + warpInQ;
    if (t >= tEnd) return;

    // ---- Prologue ----
    int sv = 0, dv = 0;
    if (lane < 16) {
        int2 ed = __ldg(&g_bedge[t * 16 + lane]);
        sv = ed.x; dv = ed.y;
    }
    int sA = __shfl_sync(0xffffffffu, sv, nq);
    int sB = __shfl_sync(0xffffffffu, sv, nq + 8);
    uint4 uA = *reinterpret_cast<const uint4*>(h + (size_t)sA * DD + 8 * p);
    uint4 uB = *reinterpret_cast<const uint4*>(h + (size_t)sB * DD + 8 * p);

    for (; t < tEnd; ) {
        const int tn = t + qWarps;
        // ---- Next tile's loads ----
        int nsv = 0, ndv = 0;
        if (tn < tEnd && lane < 16) {
            int2 ed = __ldg(&g_bedge[tn * 16 + lane]);
            nsv = ed.x; ndv = ed.y;
        }
        const int nsA = __shfl_sync(0xffffffffu, nsv, nq);
        const int nsB = __shfl_sync(0xffffffffu, nsv, nq + 8);
        uint4 nuA, nuB;
        if (tn < tEnd) {
            nuA = *reinterpret_cast<const uint4*>(h + (size_t)nsA * DD + 8 * p);
            nuB = *reinterpret_cast<const uint4*>(h + (size_t)nsB * DD + 8 * p);
        }

        // ---- Compute current tile ----
        unsigned A0[4], A1[4];
        if (RELU) {
            A0[0] = relu_u(uA.x); A0[1] = relu_u(uB.x);
            A0[2] = relu_u(uA.y); A0[3] = relu_u(uB.y);
            A1[0] = relu_u(uA.z); A1[1] = relu_u(uB.z);
            A1[2] = relu_u(uA.w); A1[3] = relu_u(uB.w);
        } else {
            A0[0] = uA.x; A0[1] = uB.x; A0[2] = uA.y; A0[3] = uB.y;
            A1[0] = uA.z; A1[1] = uB.z; A1[2] = uA.w; A1[3] = uB.w;
        }

        float acc[4][4];
#pragma unroll
        for (int g = 0; g < 4; g++) {
            acc[g][0] = 0.f; acc[g][1] = 0.f; acc[g][2] = 0.f; acc[g][3] = 0.f;
        }
#pragma unroll
        for (int g = 0; g < 4; g++) {
            mma16816(acc[g], A0, bf[g][0]);
            mma16816(acc[g], A1, bf[g][1]);
        }

        const int dA = __shfl_sync(0xffffffffu, dv, nq);
        const int dB = __shfl_sync(0xffffffffu, dv, nq + 8);

        // Layout L: lane's 4 o-pairs (g=0..3) are contiguous at 8p -> direct RED
        __half* pA = agg + (size_t)dA * DD + 8 * p;
        asm volatile("red.global.add.noftz.v4.f16x2 [%0], {%1, %2, %3, %4};"
                     :: "l"(pA),
                        "r"(pack_h2(acc[0][0], acc[0][1])),
                        "r"(pack_h2(acc[1][0], acc[1][1])),
                        "r"(pack_h2(acc[2][0], acc[2][1])),
                        "r"(pack_h2(acc[3][0], acc[3][1]))
                     : "memory");
        __half* pB = agg + (size_t)dB * DD + 8 * p;
        asm volatile("red.global.add.noftz.v4.f16x2 [%0], {%1, %2, %3, %4};"
                     :: "l"(pB),
                        "r"(pack_h2(acc[0][2], acc[0][3])),
                        "r"(pack_h2(acc[1][2], acc[1][3])),
                        "r"(pack_h2(acc[2][2], acc[2][3])),
                        "r"(pack_h2(acc[3][2], acc[3][3]))
                     : "memory");

        // ---- Rotate ----
        t = tn;
        sv = nsv; dv = ndv;
        uA = nuA; uB = nuB;
    }
}

// ---------------------------------------------------------------------------
// mean: out[m][f(j)] = mean_a relu(agg[m*32+a][j])  (agg in layout L)
// ---------------------------------------------------------------------------
__global__ void mean_kernel(const __half* __restrict__ agg,
                            float* __restrict__ out, int M)
{
    int j = threadIdx.x & 31;
    int m = (blockIdx.x * blockDim.x + threadIdx.x) >> 5;
    if (m >= M) return;
    float s = 0.0f;
#pragma unroll
    for (int a = 0; a < 32; a++)
        s += fmaxf(__half2float(agg[((size_t)m * 32 + a) * DD + j]), 0.0f);
    // invert layout L: position j -> feature f
    const int f = 2 * (j >> 3) + 8 * ((j & 7) >> 1) + (j & 1);
    out[(size_t)m * DD + f] = s * (1.0f / 32.0f);
}

// ---------------------------------------------------------------------------
extern "C" void kernel_launch(void* const* d_in, const int* in_sizes, int n_in,
                              void* d_out, int out_size)
{
    const float* x    = (const float*)d_in[0];
    const float* W    = (const float*)d_in[1];
    const float* Wl   = (const float*)d_in[2];
    const float* bias = (const float*)d_in[3];
    const int*   src  = (const int*)d_in[4];
    const int*   dst  = (const int*)d_in[5];
    const int*   et   = (const int*)d_in[6];
    float* out = (float*)d_out;

    const int N = in_sizes[0] / DD;
    const int E = in_sizes[4];
    const int M = out_size / DD;
    const int nTilesN = N / 16;
    const int nb = (E + HIST_CHUNK - 1) / HIST_CHUNK;

    void *hP = nullptr, *aP = nullptr, *bP = nullptr;
    cudaGetSymbolAddress(&hP, g_h16);
    cudaGetSymbolAddress(&aP, g_aggA);
    cudaGetSymbolAddress(&bP, g_aggB);
    __half* h16  = (__half*)hP;
    __half* aggA = (__half*)aP;
    __half* aggB = (__half*)bP;

    const int projBlocks = 1024;
    const int edgeBlocks = 8192;   // 4 quarters x 2048
    const int meanBlocks = (M * 32 + 255) / 256;

    // ---- Bin edges by etype (once; reused by both layers) ----
    bin_hist_kernel<<<nb, 256>>>(et, E);
    bin_scan_kernel<<<1, 1024>>>(nb, N);
    bin_scatter_kernel<<<nb, 256>>>(src, dst, et, E);

    // ---- Layer 1 ----
    proj1_kernel<<<projBlocks, 256>>>(x, Wl, bias, h16, aggA, nTilesN);
    edge_mma_kernel<false><<<edgeBlocks, 256>>>(h16, W, aggA);

    // ---- Layer 2 (gathers relu(aggA) directly) ----
    proj2_kernel<<<projBlocks, 256>>>(aggA, Wl, bias, aggB, nTilesN);
    edge_mma_kernel<true><<<edgeBlocks, 256>>>(aggA, W, aggB);

    // ---- Per-molecule mean (relu fused) ----
    mean_kernel<<<meanBlocks, 256>>>(aggB, out, M);
}